// round 14
// baseline (speedup 1.0000x reference)
#include <cuda_runtime.h>
#include <cuda_bf16.h>
#include <math_constants.h>
#include <stdint.h>

#define BATCH 8
#define DIM 1024
#define NPTS 4096
#define KCL 32
#define HID 512
#define PRJ 128
#define EPSS 1e-3f
#define INV_EPS 1000.0f
#define LOGP_C (-8.3177252f)
#define LOGQ_C (-3.4657356f)

constexpr long OFF_LS=0, OFF_ST=1048576, OFF_COST=2097152, OFF_COSTT=3145728;
constexpr long OFF_POOL=4194304, OFF_Z1=4202496, OFF_Z2=4206592, OFF_BN=4210688;
// ---- contiguous zero-tail ----
constexpr long OFF_VLAD=4216832, OFF_PI=4478976, OFF_U=4479232, OFF_V=4512000;
constexpr long OFF_RMU=4512256, OFF_ACC=4512512, OFF_DSUM=4513536, OFF_RN=4513568;
constexpr long OFF_P1=4546336, OFF_P2=4677408;
constexpr long SCRATCH_SZ=4808480;
constexpr long ZTAIL=SCRATCH_SZ-OFF_VLAD;

static __device__ float d_scratch[SCRATCH_SZ];
static __device__ int   d_flags[4];
static __device__ __nv_bfloat16 d_FTh[33554432], d_FTl[33554432]; // F^T [b][n][1024]
static __device__ __nv_bfloat16 d_Fh[33554432],  d_Fl[33554432];  // F   [b][d][4096]
static __device__ __nv_bfloat16 d_Wh[802816],    d_Wl[802816];
static __device__ __nv_bfloat16 d_SCh[1048576],  d_SCl[1048576];  // score^T [b][k][4096]
static __device__ __nv_bfloat16 d_VTh[262144],   d_VTl[262144];   // vlad^T  [b][k][1024]
static __device__ float d_YT[16777216];                           // [pt][512] G1 out
static __device__ float d_YT2[16777216];                          // [pt][512] G2 out

__device__ __forceinline__ uint32_t smem_u32(const void* p){
    uint32_t a; asm("{ .reg .u64 t; cvta.to.shared.u64 t,%1; cvt.u32.u64 %0,t; }":"=r"(a):"l"(p)); return a;
}
#define CP16(dst,src) asm volatile("cp.async.cg.shared.global [%0],[%1],16;"::"r"(dst),"l"(src):"memory")
#define CPCOMMIT() asm volatile("cp.async.commit_group;":::"memory")
#define CPWAIT1() asm volatile("cp.async.wait_group 1;":::"memory")
#define CPWAIT0() asm volatile("cp.async.wait_group 0;":::"memory")
#define LDM4(r0,r1,r2,r3,ad) asm volatile("ldmatrix.sync.aligned.m8n8.x4.shared.b16 {%0,%1,%2,%3},[%4];":"=r"(r0),"=r"(r1),"=r"(r2),"=r"(r3):"r"(ad))
#define STS64v(a,r0,r1) asm volatile("st.shared.v2.b32 [%0],{%1,%2};"::"r"(a),"r"(r0),"r"(r1):"memory")
#define MMA(d,a,b) asm volatile("mma.sync.aligned.m16n8k16.row.col.f32.bf16.bf16.f32 {%0,%1,%2,%3},{%4,%5,%6,%7},{%8,%9},{%0,%1,%2,%3};" \
  :"+f"((d)[0]),"+f"((d)[1]),"+f"((d)[2]),"+f"((d)[3]) \
  :"r"((a)[0]),"r"((a)[1]),"r"((a)[2]),"r"((a)[3]),"r"((b)[0]),"r"((b)[1]))

__device__ __forceinline__ void gbar(unsigned* cnt, unsigned* gen, unsigned nb){
    __syncthreads();
    if (threadIdx.x==0){
        unsigned g = *((volatile unsigned*)gen);
        __threadfence();
        if (atomicAdd(cnt,1u)==nb-1u){ *cnt=0u; __threadfence(); atomicAdd(gen,1u); }
        else { while (*((volatile unsigned*)gen)==g) {} }
    }
    __syncthreads();
}
__device__ __forceinline__ uint32_t pk(float v0, float v1){
    __nv_bfloat162 h(__float2bfloat16(v0),__float2bfloat16(v1));
    return *(uint32_t*)&h;
}

// Y[row,ch] = sum_k A[row,k]*B[ch,k], bf16x3 split, fp32 acc.
// BNA: A is fp32 Af with relu(bna*x+bnc) + h/l split done in the load path.
template<int KTOT,int BN,int WM,int WN,int CHTOT,bool BIAS,bool BNA>
__global__ void __launch_bounds__(256,1)
hmma_gemm(const __nv_bfloat16* __restrict__ Ah, const __nv_bfloat16* __restrict__ Al, long sAb,
          const float* __restrict__ Af, const float* __restrict__ bna, const float* __restrict__ bnc,
          const __nv_bfloat16* __restrict__ Bh, const __nv_bfloat16* __restrict__ Bl, long sBb,
          float* __restrict__ Y, long sYb, const float* __restrict__ bias)
{
    constexpr int MI = 128/(WM*16), NI = BN/(WN*8);
    constexpr int KT = KTOT/32;
    constexpr int SS = 20480 + BN*160;
    extern __shared__ __align__(16) char smem[];
    const uint32_t sm0 = smem_u32(smem);
    const int tid=threadIdx.x, lane=tid&31, w=tid>>5;
    const int wm = w % WM, wn = w / WM;
    const int b=blockIdx.z, pt0=blockIdx.y*128, ch0=blockIdx.x*BN;

    const __nv_bfloat16* pAh = BNA ? nullptr : Ah + b*sAb + (long)pt0*KTOT;
    const __nv_bfloat16* pAl = BNA ? nullptr : Al + b*sAb + (long)pt0*KTOT;
    const float*         pAf = BNA ? Af + b*sAb + (long)pt0*KTOT : nullptr;
    const __nv_bfloat16* pBh = Bh + b*sBb + (long)ch0*KTOT;
    const __nv_bfloat16* pBl = Bl + b*sBb + (long)ch0*KTOT;
    float* Yb = Y + b*sYb;

    float acc[MI][NI][4];
#pragma unroll
    for(int i=0;i<MI;i++)
#pragma unroll
        for(int j=0;j<NI;j++){ acc[i][j][0]=0.f;acc[i][j][1]=0.f;acc[i][j][2]=0.f;acc[i][j][3]=0.f; }

    float4 av[4];
    auto loadA_regs = [&](int t){
        const int k0 = t*32;
#pragma unroll
        for (int i=0;i<4;i++){
            int idx = tid + i*256; int r = idx>>3, c = idx&7;
            av[i] = *(const float4*)(pAf + (long)r*KTOT + k0 + c*4);
        }
    };
    auto stsA = [&](int t){
        const uint32_t st = sm0 + (t&1)*SS;
        const int k0 = t*32;
#pragma unroll
        for (int i=0;i<4;i++){
            int idx = tid + i*256; int r = idx>>3, c = idx&7;
            int ch = k0 + c*4;
            float v0=fmaxf(fmaf(__ldg(bna+ch),  av[i].x,__ldg(bnc+ch)),  0.f);
            float v1=fmaxf(fmaf(__ldg(bna+ch+1),av[i].y,__ldg(bnc+ch+1)),0.f);
            float v2=fmaxf(fmaf(__ldg(bna+ch+2),av[i].z,__ldg(bnc+ch+2)),0.f);
            float v3=fmaxf(fmaf(__ldg(bna+ch+3),av[i].w,__ldg(bnc+ch+3)),0.f);
            __nv_bfloat16 h0=__float2bfloat16(v0),h1=__float2bfloat16(v1);
            __nv_bfloat16 h2=__float2bfloat16(v2),h3=__float2bfloat16(v3);
            uint32_t H0=pk(v0,v1), H1=pk(v2,v3);
            uint32_t L0=pk(v0-__bfloat162float(h0), v1-__bfloat162float(h1));
            uint32_t L1=pk(v2-__bfloat162float(h2), v3-__bfloat162float(h3));
            uint32_t ad = st + r*80 + c*8;
            STS64v(ad, H0, H1);
            STS64v(ad+10240, L0, L1);
        }
    };
    auto load_stage = [&](int t){
        const int k0 = t*32;
        const uint32_t st = sm0 + (t&1)*SS;
        if (!BNA){
#pragma unroll
            for (int i=0;i<2;i++){
                int idx = tid + i*256; int r = idx>>2, c = idx&3;
                CP16(st + r*80 + c*16,         pAh + (long)r*KTOT + k0 + c*8);
                CP16(st + 10240 + r*80 + c*16, pAl + (long)r*KTOT + k0 + c*8);
            }
        }
#pragma unroll
        for (int i=0;i<(BN*4+255)/256;i++){
            int idx = tid + i*256;
            if ((BN*4)%256==0 || idx<BN*4){
                int r = idx>>2, c = idx&3;
                CP16(st + 20480 + r*80 + c*16,         pBh + (long)r*KTOT + k0 + c*8);
                CP16(st + 20480 + BN*80 + r*80 + c*16, pBl + (long)r*KTOT + k0 + c*8);
            }
        }
        CPCOMMIT();
    };

    if (BNA) loadA_regs(0);
    load_stage(0);
    if (KT>1) load_stage(1);

    for (int t=0;t<KT;t++){
        if (BNA) stsA(t);
        if (t==KT-1) { CPWAIT0(); } else { CPWAIT1(); }
        __syncthreads();
        if (BNA && t+1<KT) loadA_regs(t+1);
        const uint32_t st = sm0 + (t&1)*SS;
#pragma unroll
        for (int ks=0;ks<2;ks++){
            const int kk=ks*16;
            uint32_t ah[MI][4], al[MI][4], bh[NI][2], bl[NI][2];
            const uint32_t koff = (kk + ((lane>>4)<<3))*2;
            uint32_t abase = st + (wm*MI*16 + (lane&15))*80 + koff;
#pragma unroll
            for (int mi=0;mi<MI;mi++){
                LDM4(ah[mi][0],ah[mi][1],ah[mi][2],ah[mi][3], abase + mi*16*80);
                LDM4(al[mi][0],al[mi][1],al[mi][2],al[mi][3], abase + mi*16*80 + 10240);
            }
            uint32_t bbase = st + 20480 + (wn*NI*8 + (lane&15))*80 + koff;
#pragma unroll
            for (int nj=0;nj<NI/2;nj++){
                uint32_t r0,r1,r2,r3;
                LDM4(r0,r1,r2,r3, bbase + nj*16*80);
                bh[2*nj][0]=r0; bh[2*nj][1]=r2; bh[2*nj+1][0]=r1; bh[2*nj+1][1]=r3;
                LDM4(r0,r1,r2,r3, bbase + nj*16*80 + BN*80);
                bl[2*nj][0]=r0; bl[2*nj][1]=r2; bl[2*nj+1][0]=r1; bl[2*nj+1][1]=r3;
            }
#pragma unroll
            for (int mi=0;mi<MI;mi++)
#pragma unroll
                for (int ni=0;ni<NI;ni++){
                    MMA(acc[mi][ni], ah[mi], bh[ni]);
                    MMA(acc[mi][ni], ah[mi], bl[ni]);
                    MMA(acc[mi][ni], al[mi], bh[ni]);
                }
        }
        __syncthreads();
        if (t+2 < KT) load_stage(t+2);
    }

    const int rbase = pt0 + wm*MI*16 + (lane>>2);
    const int cbase = ch0 + wn*NI*8 + (lane&3)*2;
#pragma unroll
    for (int mi=0;mi<MI;mi++)
#pragma unroll
        for (int ni=0;ni<NI;ni++){
            int r = rbase + mi*16, c = cbase + ni*8;
            float bv0 = BIAS ? bias[c] : 0.f, bv1 = BIAS ? bias[c+1] : 0.f;
            float* y0 = Yb + (long)r*CHTOT + c;
            y0[0]=acc[mi][ni][0]+bv0; y0[1]=acc[mi][ni][1]+bv1;
            float* y1 = y0 + 8*CHTOT;
            y1[0]=acc[mi][ni][2]+bv0; y1[1]=acc[mi][ni][3]+bv1;
        }
}

__global__ void w_split(const float* __restrict__ w1, const float* __restrict__ w2,
                        const float* __restrict__ w3, __nv_bfloat16* __restrict__ H,
                        __nv_bfloat16* __restrict__ L){
    int i=blockIdx.x*256+threadIdx.x; if(i>=802816) return;
    float v = (i<524288)? w1[i] : (i<786432? w2[i-524288] : w3[i-786432]);
    __nv_bfloat16 h=__float2bfloat16(v); H[i]=h; L[i]=__float2bfloat16(v-__bfloat162float(h));
}
__global__ void ft_split(const float* __restrict__ F, __nv_bfloat16* __restrict__ TH,
                         __nv_bfloat16* __restrict__ TL, __nv_bfloat16* __restrict__ DH,
                         __nv_bfloat16* __restrict__ DL, float* __restrict__ rn){
    __shared__ float t[32][33];
    __shared__ float part[8][32];
    int b=blockIdx.z, n0=blockIdx.x*32, d0=blockIdx.y*32, tx=threadIdx.x, ty=threadIdx.y;
    const float* Fb=F+((long)b<<22);
#pragma unroll
    for (int j=0;j<4;j++){
        float v=Fb[(long)(d0+ty*4+j)*4096+n0+tx];
        t[ty*4+j][tx]=v;
        long od=((long)(b*1024)+d0+ty*4+j)*4096+n0+tx;
        __nv_bfloat16 h=__float2bfloat16(v); DH[od]=h; DL[od]=__float2bfloat16(v-__bfloat162float(h));
    }
    __syncthreads();
    float s=0.f;
#pragma unroll
    for (int j=0;j<4;j++){
        float v=t[tx][ty*4+j];
        long o=((long)(b*4096)+n0+ty*4+j)*1024+d0+tx;
        __nv_bfloat16 h=__float2bfloat16(v); TH[o]=h; TL[o]=__float2bfloat16(v-__bfloat162float(h));
        float w2=t[ty*4+j][tx]; s=fmaf(w2,w2,s);
    }
    part[ty][tx]=s; __syncthreads();
    if (ty==0){
        float tot=0.f;
#pragma unroll
        for(int k=0;k<8;k++) tot+=part[k][tx];
        atomicAdd(&rn[(b<<12)+n0+tx], tot);
    }
}
__global__ void bnT_partial(const float* __restrict__ Y, float* __restrict__ acc){
    int ch=threadIdx.x; long r0=(long)blockIdx.x*256;
    const float* p=Y+r0*512+ch;
    float s=0.f,s2=0.f;
    for (int r=0;r<256;r++){ float v=p[(long)r*512]; s+=v; s2=fmaf(v,v,s2); }
    atomicAdd(&acc[ch],s); atomicAdd(&acc[512+ch],s2);
}
__global__ void bnT_final(float* __restrict__ acc, const float* __restrict__ g,
                          const float* __restrict__ bb, float* __restrict__ aO, float* __restrict__ cO){
    int ch=threadIdx.x;
    float inv=1.f/32768.f, mean=acc[ch]*inv, var=acc[512+ch]*inv-mean*mean;
    float a=g[ch]*rsqrtf(var+1e-5f);
    aO[ch]=a; cO[ch]=bb[ch]-a*mean; acc[ch]=0.f; acc[512+ch]=0.f;
}
// one reset kernel: zero-tail + out + flags
__global__ void reset_k(float* __restrict__ zt, long nz, float* __restrict__ o, long no,
                        int* __restrict__ fl){
    long i=(long)blockIdx.x*256+threadIdx.x;
    if (i<nz) zt[i]=0.f;
    else if (i<nz+no) o[i-nz]=0.f;
    if (i<4) fl[i]=0;
}

template<int BM,int BN,int BK,int TM,int TN,bool TA,int SPLITK>
__global__ void __launch_bounds__((BM/TM)*(BN/TN))
gemm_k(const float* __restrict__ A, long strideA, int lda,
       const float* __restrict__ B, long strideB,
       float* __restrict__ C, long strideC, int M, int Nn, int Kk,
       const float* __restrict__ bias, const float* __restrict__ bnS, const float* __restrict__ bnB)
{
    constexpr int THREADS=(BM/TM)*(BN/TN);
    const int bz=blockIdx.z, batch=bz/SPLITK, split=bz%SPLITK;
    const int kPer=Kk/SPLITK, kBeg=split*kPer, kEnd=kBeg+kPer;
    const float* Ap=A+(long)batch*strideA;
    const float* Bp=B+(long)batch*strideB;
    float* Cp=C+(long)batch*strideC;
    __shared__ __align__(16) float As[BK][BM+4];
    __shared__ __align__(16) float Bs[BK][BN+4];
    const int tid=threadIdx.x, tx=tid%(BN/TN), ty=tid/(BN/TN);
    const int m0=blockIdx.y*BM, n0=blockIdx.x*BN;
    float acc[TM][TN];
#pragma unroll
    for(int i=0;i<TM;i++)
#pragma unroll
        for(int j=0;j<TN;j++) acc[i][j]=0.f;
    for (int k0=kBeg;k0<kEnd;k0+=BK){
        if (!TA){ for(int i=tid;i<BM*BK;i+=THREADS){ int mm=i/BK,kk=i%BK; As[kk][mm]=Ap[(long)(m0+mm)*lda+(k0+kk)]; } }
        else    { for(int i=tid;i<BM*BK;i+=THREADS){ int kk=i/BM,mm=i%BM; As[kk][mm]=Ap[(long)(k0+kk)*lda+(m0+mm)]; } }
        for(int i=tid;i<BK*BN;i+=THREADS){
            int kk=i/BN,nn=i%BN;
            float v=Bp[(long)(k0+kk)*Nn+(n0+nn)];
            if (bnS){ int gk=k0+kk; v=fmaxf(fmaf(bnS[gk],v,bnB[gk]),0.f); }
            Bs[kk][nn]=v;
        }
        __syncthreads();
#pragma unroll
        for (int kk=0;kk<BK;kk++){
            float ra[TM],rb[TN];
#pragma unroll
            for(int h=0;h<TM/4;h++) *(float4*)(ra+4*h)=*(const float4*)(&As[kk][ty*TM+4*h]);
#pragma unroll
            for(int h=0;h<TN/4;h++) *(float4*)(rb+4*h)=*(const float4*)(&Bs[kk][tx*TN+4*h]);
#pragma unroll
            for(int i=0;i<TM;i++)
#pragma unroll
                for(int j=0;j<TN;j++) acc[i][j]=fmaf(ra[i],rb[j],acc[i][j]);
        }
        __syncthreads();
    }
#pragma unroll
    for (int i=0;i<TM;i++){
        int m=m0+ty*TM+i; float bv=bias?bias[m]:0.f;
#pragma unroll
        for (int j=0;j<TN;j++){
            int n=n0+tx*TN+j;
            if (SPLITK==1) Cp[(long)m*Nn+n]=acc[i][j]+bv;
            else atomicAdd(&Cp[(long)m*Nn+n],acc[i][j]+((split==0)?bv:0.f));
        }
    }
}

__global__ void bnproj_stats(const float* __restrict__ Y, const float* __restrict__ g,
                             const float* __restrict__ bb, float* __restrict__ aO,
                             float* __restrict__ cO, int Ch){
    int w=blockIdx.x*8+(threadIdx.x>>5), lane=threadIdx.x&31;
    if (w>=Ch) return;
    float s=0.f,s2=0.f;
#pragma unroll
    for(int b=0;b<BATCH;b++){ float v=Y[(((long)b*Ch+w)<<5)+lane]; s+=v; s2=fmaf(v,v,s2); }
#pragma unroll
    for(int o=16;o;o>>=1){ s+=__shfl_xor_sync(~0u,s,o); s2+=__shfl_xor_sync(~0u,s2,o); }
    if (lane==0){
        float inv=1.f/256.f, mean=s*inv, var=s2*inv-mean*mean;
        float a=g[w]*rsqrtf(var+1e-5f); aO[w]=a; cO[w]=bb[w]-a*mean;
    }
}
__global__ void bn2_stats(const float* __restrict__ Z, const float* __restrict__ g,
                          const float* __restrict__ bb, float* __restrict__ aO,
                          float* __restrict__ cO, int Ch){
    int ch=blockIdx.x*256+threadIdx.x; if(ch>=Ch) return;
    float s=0.f;
#pragma unroll
    for(int b=0;b<BATCH;b++) s+=Z[(long)b*Ch+ch];
    float mean=s*0.125f, v=0.f;
#pragma unroll
    for(int b=0;b<BATCH;b++){ float d=Z[(long)b*Ch+ch]-mean; v=fmaf(d,d,v); }
    v*=0.125f;
    float a=g[ch]*rsqrtf(v+1e-5f); aO[ch]=a; cO[ch]=bb[ch]-a*mean;
}
// softmax over K=32 (warp per point) + pi + direct transposed bf16 split output
__global__ void __launch_bounds__(1024)
softmax_tr(const float* __restrict__ ls, float* __restrict__ sT, float* __restrict__ pi,
           __nv_bfloat16* __restrict__ SH, __nv_bfloat16* __restrict__ SL){
    __shared__ float spi[32];
    __shared__ float tile[32][33];
    const int tid=threadIdx.x, w=tid>>5, lane=tid&31;
    const int b=blockIdx.x>>7, n0=(blockIdx.x&127)<<5;
    if (tid<32) spi[tid]=0.f;
    __syncthreads();
    const long pt=(long)(b<<12)+n0+w;
    float x=ls[(pt<<5)+lane], m=x;
#pragma unroll
    for(int o=16;o;o>>=1) m=fmaxf(m,__shfl_xor_sync(~0u,m,o));
    float e=__expf(x-m), s=e;
#pragma unroll
    for(int o=16;o;o>>=1) s+=__shfl_xor_sync(~0u,s,o);
    float pr=e/s;
    sT[(pt<<5)+lane]=pr;
    tile[w][lane]=pr;
    atomicAdd(&spi[lane],pr);
    __syncthreads();
    if (tid<32) atomicAdd(&pi[(b<<5)+tid],spi[tid]);
    // transpose-write: warp w emits cluster k=w, lanes cover the 32 points
    float v=tile[lane][w];
    long o=((long)((b<<5)+w)<<12)+n0+lane;
    __nv_bfloat16 h=__float2bfloat16(v);
    SH[o]=h; SL[o]=__float2bfloat16(v-__bfloat162float(h));
}
// scale vlad by 1/pi, max-pool, accumulate Σv² into rmu, emit vlad^T bf16 split
__global__ void vlad_fin(float* __restrict__ vlad, const float* __restrict__ pi,
                         float* __restrict__ pool, float* __restrict__ rmu,
                         __nv_bfloat16* __restrict__ VH, __nv_bfloat16* __restrict__ VL){
    int b=blockIdx.y, d=blockIdx.x*256+threadIdx.x;
    __shared__ float ip[32];
    __shared__ float rmacc[32];
    if (threadIdx.x<32){ ip[threadIdx.x]=1.f/fmaxf(pi[(b<<5)+threadIdx.x],1e-4f); rmacc[threadIdx.x]=0.f; }
    __syncthreads();
    float4* vp=(float4*)(vlad+(((long)((b<<10)+d))<<5));
    float val[32];
    float mx=-CUDART_INF_F;
#pragma unroll
    for(int q=0;q<8;q++){
        float4 v=vp[q];
        v.x*=ip[4*q]; v.y*=ip[4*q+1]; v.z*=ip[4*q+2]; v.w*=ip[4*q+3];
        val[4*q]=v.x; val[4*q+1]=v.y; val[4*q+2]=v.z; val[4*q+3]=v.w;
        mx=fmaxf(mx,fmaxf(fmaxf(v.x,v.y),fmaxf(v.z,v.w)));
        vp[q]=v;
        atomicAdd(&rmacc[4*q],v.x*v.x); atomicAdd(&rmacc[4*q+1],v.y*v.y);
        atomicAdd(&rmacc[4*q+2],v.z*v.z); atomicAdd(&rmacc[4*q+3],v.w*v.w);
    }
    pool[(b<<10)+d]=mx;
#pragma unroll
    for(int k=0;k<32;k++){
        long o=((long)((b<<5)+k)<<10)+d;
        __nv_bfloat16 h=__float2bfloat16(val[k]);
        VH[o]=h; VL[o]=__float2bfloat16(val[k]-__bfloat162float(h));
    }
    __syncthreads();
    if (threadIdx.x<32) atomicAdd(&rmu[(b<<5)+threadIdx.x],rmacc[threadIdx.x]);
}
// finalize cost: rn/rmu are Σ² accumulators -> rsqrt inline; write both layouts
__global__ void cost_fin(float* __restrict__ cost, float* __restrict__ costT,
                         const float* __restrict__ rnacc, const float* __restrict__ rmuacc){
    int b=blockIdx.y, n=blockIdx.x*256+threadIdx.x;
    __shared__ float rm[32];
    if (threadIdx.x<32) rm[threadIdx.x]=1.f/fmaxf(sqrtf(rmuacc[(b<<5)+threadIdx.x]),1e-12f);
    __syncthreads();
    float r2=2.f/fmaxf(sqrtf(rnacc[(b<<12)+n]),1e-12f);
    float4* cp=(float4*)(cost+(((long)((b<<12)+n))<<5));
    float val[32];
#pragma unroll
    for(int q=0;q<8;q++){
        float4 v=cp[q];
        val[4*q]=2.f-v.x*r2*rm[4*q]; val[4*q+1]=2.f-v.y*r2*rm[4*q+1];
        val[4*q+2]=2.f-v.z*r2*rm[4*q+2]; val[4*q+3]=2.f-v.w*r2*rm[4*q+3];
        cp[q]=make_float4(val[4*q],val[4*q+1],val[4*q+2],val[4*q+3]);
    }
#pragma unroll
    for(int k=0;k<32;k++) costT[(((long)((b<<5)+k))<<12)+n]=val[k];
}

__global__ void __launch_bounds__(128)
sinkhorn_fused(const float* __restrict__ cost, const float* __restrict__ costT,
               const float* __restrict__ sT, float* __restrict__ u,
               float* __restrict__ v, float* __restrict__ dsum,
               unsigned* __restrict__ bar, float* __restrict__ out0)
{
    const int tid=threadIdx.x, bid=blockIdx.x;
    const int p = bid*128+tid;
    const int b = p>>12;
    __shared__ float red[128];
    __shared__ float sm[128], ssx[128];
    for (int it=0; it<25; ++it){
        {
            const float* vb = v + (b<<5);
            const float4* cp=(const float4*)(cost+((long)p<<5));
            float t[32];
#pragma unroll
            for(int q=0;q<8;q++){
                float4 c4=cp[q];
                t[4*q]=vb[4*q]-c4.x; t[4*q+1]=vb[4*q+1]-c4.y;
                t[4*q+2]=vb[4*q+2]-c4.z; t[4*q+3]=vb[4*q+3]-c4.w;
            }
            float m=t[0];
#pragma unroll
            for(int k=1;k<32;k++) m=fmaxf(m,t[k]);
            float s=0.f;
#pragma unroll
            for(int k=0;k<32;k++) s+=__expf((t[k]-m)*INV_EPS);
            float un=EPSS*LOGP_C-m-EPSS*__logf(s);
            float dl=fabsf(un-u[p]); u[p]=un;
            red[tid]=dl; __syncthreads();
            for(int st=64;st;st>>=1){ if(tid<st) red[tid]+=red[tid+st]; __syncthreads(); }
            if (tid==0) atomicAdd(&dsum[it],red[0]);
        }
        gbar(bar,bar+1,256u);
        {
            const float* row=costT+((long)bid<<12);
            const float* ub=u+((bid>>5)<<12);
            float mm=-CUDART_INF_F, ss=0.f;
            for(int i=tid;i<NPTS;i+=128){
                float x=ub[i]-row[i];
                if (x>mm){ ss=ss*__expf((mm-x)*INV_EPS)+1.f; mm=x; } else ss+=__expf((x-mm)*INV_EPS);
            }
            sm[tid]=mm; ssx[tid]=ss; __syncthreads();
            for(int st=64;st;st>>=1){
                if(tid<st){
                    float m1=sm[tid],s1=ssx[tid],m2=sm[tid+st],s2=ssx[tid+st];
                    float M=fmaxf(m1,m2);
                    ssx[tid]=s1*__expf((m1-M)*INV_EPS)+s2*__expf((m2-M)*INV_EPS);
                    sm[tid]=M;
                }
                __syncthreads();
            }
            if (tid==0){
                float vn=EPSS*LOGQ_C-sm[0]-EPSS*__logf(ssx[0]);
                atomicAdd(&dsum[it],fabsf(vn-v[bid]));
                v[bid]=vn;
            }
        }
        gbar(bar,bar+1,256u);
        float dd = *((volatile float*)&dsum[it]);
        if (dd*0.125f < 1e-3f) break;
    }
    {
        const float* vb = v + (b<<5);
        float uu = u[p];
        const float4* cp=(const float4*)(cost+((long)p<<5));
        const float4* sp=(const float4*)(sT+((long)p<<5));
        float acc=0.f;
#pragma unroll
        for(int q=0;q<8;q++){
            float4 c4=cp[q]; float4 s4=sp[q];
            acc+=__expf((uu+vb[4*q]-c4.x)*INV_EPS)*__logf(fmaxf(s4.x,1e-38f));
            acc+=__expf((uu+vb[4*q+1]-c4.y)*INV_EPS)*__logf(fmaxf(s4.y,1e-38f));
            acc+=__expf((uu+vb[4*q+2]-c4.z)*INV_EPS)*__logf(fmaxf(s4.z,1e-38f));
            acc+=__expf((uu+vb[4*q+3]-c4.w)*INV_EPS)*__logf(fmaxf(s4.w,1e-38f));
        }
        red[tid]=acc; __syncthreads();
        for(int st=64;st;st>>=1){ if(tid<st) red[tid]+=red[tid+st]; __syncthreads(); }
        if (tid==0) atomicAdd(out0,red[0]*(-0.125f));
    }
}

template<bool ACT>
__global__ void fc_k(const float* __restrict__ X, const float* __restrict__ W,
                     float* __restrict__ C, int O, int Kin, const float* __restrict__ bias,
                     const float* __restrict__ a, const float* __restrict__ c){
    int gw=(blockIdx.x*256+threadIdx.x)>>5, lane=threadIdx.x&31;
    int b=gw/O, o=gw-b*O;
    const float* x=X+(long)b*Kin;
    const float* wr=W+(long)o*Kin;
    float s=0.f;
    for(int k=lane;k<Kin;k+=32){
        float xv=x[k];
        if (ACT) xv=fmaxf(fmaf(a[k],xv,c[k]),0.f);
        s=fmaf(xv,wr[k],s);
    }
#pragma unroll
    for(int o2=16;o2;o2>>=1) s+=__shfl_xor_sync(~0u,s,o2);
    if(lane==0) C[(long)b*O+o]=s+(bias?bias[o]:0.f);
}

extern "C" void kernel_launch(void* const* d_in, const int* in_sizes, int n_in,
                              void* d_out, int out_size)
{
    const float *F=(const float*)d_in[0];
    const float *cw1=(const float*)d_in[1], *cg1=(const float*)d_in[3], *ct1=(const float*)d_in[4];
    const float *cw2=(const float*)d_in[5], *cg2=(const float*)d_in[7], *ct2=(const float*)d_in[8];
    const float *cw3=(const float*)d_in[9], *cb3=(const float*)d_in[10];
    const float *pw1=(const float*)d_in[11], *pg1=(const float*)d_in[13], *pt1=(const float*)d_in[14];
    const float *pw2=(const float*)d_in[15], *pg2=(const float*)d_in[17], *pt2=(const float*)d_in[18];
    const float *pw3=(const float*)d_in[19], *pb3=(const float*)d_in[20];
    const float *mw1=(const float*)d_in[21], *mg1=(const float*)d_in[23], *mt1=(const float*)d_in[24];
    const float *mw2=(const float*)d_in[25], *mg2=(const float*)d_in[27], *mt2=(const float*)d_in[28];
    const float *mw3=(const float*)d_in[29], *mb3=(const float*)d_in[30];
    float* out=(float*)d_out;

    static float* S=nullptr; static int* FL=nullptr;
    static __nv_bfloat16 *FTh,*FTl,*Fh,*Fl,*Wh,*Wl,*SCh,*SCl,*VTh,*VTl;
    static float *YT,*YT2;
    if (!S){
        cudaGetSymbolAddress((void**)&S,d_scratch);
        cudaGetSymbolAddress((void**)&FL,d_flags);
        cudaGetSymbolAddress((void**)&FTh,d_FTh); cudaGetSymbolAddress((void**)&FTl,d_FTl);
        cudaGetSymbolAddress((void**)&Fh,d_Fh);   cudaGetSymbolAddress((void**)&Fl,d_Fl);
        cudaGetSymbolAddress((void**)&Wh,d_Wh);   cudaGetSymbolAddress((void**)&Wl,d_Wl);
        cudaGetSymbolAddress((void**)&SCh,d_SCh); cudaGetSymbolAddress((void**)&SCl,d_SCl);
        cudaGetSymbolAddress((void**)&VTh,d_VTh); cudaGetSymbolAddress((void**)&VTl,d_VTl);
        cudaGetSymbolAddress((void**)&YT,d_YT);   cudaGetSymbolAddress((void**)&YT2,d_YT2);
        cudaFuncSetAttribute(hmma_gemm<1024,128,2,4,512,false,false>,cudaFuncAttributeMaxDynamicSharedMemorySize,81920);
        cudaFuncSetAttribute(hmma_gemm<512,128,2,4,512,false,true>,cudaFuncAttributeMaxDynamicSharedMemorySize,81920);
        cudaFuncSetAttribute(hmma_gemm<512,32,8,1,32,true,true>,cudaFuncAttributeMaxDynamicSharedMemorySize,51200);
        cudaFuncSetAttribute(hmma_gemm<4096,32,8,1,32,false,false>,cudaFuncAttributeMaxDynamicSharedMemorySize,51200);
        cudaFuncSetAttribute(hmma_gemm<1024,32,8,1,32,false,false>,cudaFuncAttributeMaxDynamicSharedMemorySize,51200);
    }
    float *LS=S+OFF_LS,*ST=S+OFF_ST,*COST=S+OFF_COST,*COSTT=S+OFF_COSTT;
    float *RN=S+OFF_RN,*POOL=S+OFF_POOL,*P1=S+OFF_P1,*P2=S+OFF_P2;
    float *Z1=S+OFF_Z1,*Z2=S+OFF_Z2,*BNC=S+OFF_BN;
    float *VLAD=S+OFF_VLAD,*PI=S+OFF_PI,*U=S+OFF_U,*V=S+OFF_V,*RMU=S+OFF_RMU;
    float *ACC=S+OFF_ACC,*DS=S+OFF_DSUM;
    float *a1=BNC,*c1=BNC+512,*a2=BNC+1024,*c2=BNC+1536;
    float *ap1=BNC+2048,*cp1=BNC+2560,*ap2=BNC+3072,*cp2=BNC+3584;
    float *am1=BNC+4096,*cm1=BNC+4608,*am2=BNC+5120,*cm2=BNC+5632;

    reset_k<<<(int)((ZTAIL+32897+255)/256),256>>>(S+OFF_VLAD,ZTAIL,out,32897,FL);
    w_split<<<3137,256>>>(cw1,cw2,cw3,Wh,Wl);
    ft_split<<<dim3(128,32,8),dim3(32,8)>>>(F,FTh,FTl,Fh,Fl,RN);

    // score head on HMMA (bf16x3); BN-relu+split fused into A-load of G2/G3
    hmma_gemm<1024,128,2,4,512,false,false><<<dim3(4,32,8),256,81920>>>(
        FTh,FTl,4194304L, nullptr,nullptr,nullptr, Wh,Wl,0L, YT,2097152L,nullptr);
    bnT_partial<<<128,512>>>(YT,ACC);
    bnT_final<<<1,512>>>(ACC,cg1,ct1,a1,c1);
    hmma_gemm<512,128,2,4,512,false,true><<<dim3(4,32,8),256,81920>>>(
        nullptr,nullptr,2097152L, YT,a1,c1, Wh+524288,Wl+524288,0L, YT2,2097152L,nullptr);
    bnT_partial<<<128,512>>>(YT2,ACC);
    bnT_final<<<1,512>>>(ACC,cg2,ct2,a2,c2);
    hmma_gemm<512,32,8,1,32,true,true><<<dim3(1,32,8),256,51200>>>(
        nullptr,nullptr,2097152L, YT2,a2,c2, Wh+786432,Wl+786432,0L, LS,131072L,cb3);

    softmax_tr<<<1024,1024>>>(LS,ST,PI,SCh,SCl);
    hmma_gemm<4096,32,8,1,32,false,false><<<dim3(1,8,8),256,51200>>>(
        Fh,Fl,4194304L, nullptr,nullptr,nullptr, SCh,SCl,131072L, VLAD,32768L,nullptr);
    vlad_fin<<<dim3(4,8),256>>>(VLAD,PI,POOL,RMU,VTh,VTl);
    hmma_gemm<1024,32,8,1,32,false,false><<<dim3(1,32,8),256,51200>>>(
        FTh,FTl,4194304L, nullptr,nullptr,nullptr, VTh,VTl,32768L, COST,131072L,nullptr);
    cost_fin<<<dim3(16,8),256>>>(COST,COSTT,RN,RMU);

    sinkhorn_fused<<<256,128>>>(COST,COSTT,ST,U,V,DS,(unsigned*)(FL+2),out);

    gemm_k<128,32,16,8,4,false,8><<<dim3(1,4,64),128>>>(
        pw1,0,DIM, VLAD,(long)DIM*KCL, P1,(long)HID*KCL, HID,KCL,DIM, nullptr,nullptr,nullptr);
    bnproj_stats<<<64,256>>>(P1,pg1,pt1,ap1,cp1,HID);
    gemm_k<128,32,16,8,4,false,8><<<dim3(1,4,64),128>>>(
        pw2,0,HID, P1,(long)HID*KCL, P2,(long)HID*KCL, HID,KCL,HID, nullptr,ap1,cp1);
    bnproj_stats<<<64,256>>>(P2,pg2,pt2,ap2,cp2,HID);
    gemm_k<64,32,16,4,4,false,8><<<dim3(1,2,64),128>>>(
        pw3,0,HID, P2,(long)HID*KCL, out+1,(long)PRJ*KCL, PRJ,KCL,HID, pb3,ap2,cp2);

    fc_k<false><<<512,256>>>(POOL,mw1,Z1,HID,DIM,nullptr,nullptr,nullptr);
    bn2_stats<<<2,256>>>(Z1,mg1,mt1,am1,cm1,HID);
    fc_k<true ><<<512,256>>>(Z1,mw2,Z2,HID,HID,nullptr,am1,cm1);
    bn2_stats<<<2,256>>>(Z2,mg2,mt2,am2,cm2,HID);
    fc_k<true ><<<128,256>>>(Z2,mw3,out+1+32768,PRJ,HID,mb3,am2,cm2);
}

// round 15
// speedup vs baseline: 1.0397x; 1.0397x over previous
#include <cuda_runtime.h>
#include <cuda_bf16.h>
#include <math_constants.h>
#include <stdint.h>

#define BATCH 8
#define DIM 1024
#define NPTS 4096
#define KCL 32
#define HID 512
#define PRJ 128
#define EPSS 1e-3f
#define INV_EPS 1000.0f
#define LOGP_C (-8.3177252f)
#define LOGQ_C (-3.4657356f)

constexpr long OFF_LS=0, OFF_ST=1048576, OFF_COST=2097152, OFF_COSTT=3145728;
constexpr long OFF_POOL=4194304, OFF_Z1=4202496, OFF_Z2=4206592, OFF_BN=4210688;
constexpr long OFF_VLAD=4216832, OFF_PI=4478976, OFF_U=4479232, OFF_V=4512000;
constexpr long OFF_RMU=4512256, OFF_ACC=4512512, OFF_DSUM=4513536, OFF_RN=4513568;
constexpr long OFF_P1=4546336, OFF_P2=4677408;
constexpr long SCRATCH_SZ=4808480;
constexpr long ZTAIL=SCRATCH_SZ-OFF_VLAD;

static __device__ float d_scratch[SCRATCH_SZ];
static __device__ int   d_flags[4];
static __device__ __nv_bfloat16 d_FTh[33554432], d_FTl[33554432];
static __device__ __nv_bfloat16 d_Fh[33554432],  d_Fl[33554432];
static __device__ __nv_bfloat16 d_Wh[802816],    d_Wl[802816];
static __device__ __nv_bfloat16 d_SCh[1048576],  d_SCl[1048576];
static __device__ __nv_bfloat16 d_VTh[262144],   d_VTl[262144];
static __device__ float d_YT[16777216];
static __device__ float d_YT2[16777216];

__device__ __forceinline__ uint32_t smem_u32(const void* p){
    uint32_t a; asm("{ .reg .u64 t; cvta.to.shared.u64 t,%1; cvt.u32.u64 %0,t; }":"=r"(a):"l"(p)); return a;
}
#define CP16(dst,src) asm volatile("cp.async.cg.shared.global [%0],[%1],16;"::"r"(dst),"l"(src):"memory")
#define CPCOMMIT() asm volatile("cp.async.commit_group;":::"memory")
#define CPWAIT1() asm volatile("cp.async.wait_group 1;":::"memory")
#define CPWAIT0() asm volatile("cp.async.wait_group 0;":::"memory")
#define LDM4(r0,r1,r2,r3,ad) asm volatile("ldmatrix.sync.aligned.m8n8.x4.shared.b16 {%0,%1,%2,%3},[%4];":"=r"(r0),"=r"(r1),"=r"(r2),"=r"(r3):"r"(ad))
#define STS64v(a,r0,r1) asm volatile("st.shared.v2.b32 [%0],{%1,%2};"::"r"(a),"r"(r0),"r"(r1):"memory")
#define MMA(d,a,b) asm volatile("mma.sync.aligned.m16n8k16.row.col.f32.bf16.bf16.f32 {%0,%1,%2,%3},{%4,%5,%6,%7},{%8,%9},{%0,%1,%2,%3};" \
  :"+f"((d)[0]),"+f"((d)[1]),"+f"((d)[2]),"+f"((d)[3]) \
  :"r"((a)[0]),"r"((a)[1]),"r"((a)[2]),"r"((a)[3]),"r"((b)[0]),"r"((b)[1]))

__device__ __forceinline__ void gbar(unsigned* cnt, unsigned* gen, unsigned nb){
    __syncthreads();
    if (threadIdx.x==0){
        unsigned g = *((volatile unsigned*)gen);
        __threadfence();
        if (atomicAdd(cnt,1u)==nb-1u){ *cnt=0u; __threadfence(); atomicAdd(gen,1u); }
        else { while (*((volatile unsigned*)gen)==g) {} }
    }
    __syncthreads();
}
__device__ __forceinline__ uint32_t pk(float v0, float v1){
    __nv_bfloat162 h(__float2bfloat16(v0),__float2bfloat16(v1));
    return *(uint32_t*)&h;
}

// Y[row,ch] = sum_k A[row,k]*B[ch,k], bf16x3 split, fp32 acc.
// BNA: A is fp32 Af with relu(bna*x+bnc) + h/l split done in the load path.
template<int KTOT,int BN,int WM,int WN,int CHTOT,bool BIAS,bool BNA>
__global__ void __launch_bounds__(256,1)
hmma_gemm(const __nv_bfloat16* __restrict__ Ah, const __nv_bfloat16* __restrict__ Al, long sAb,
          const float* __restrict__ Af, const float* __restrict__ bna, const float* __restrict__ bnc,
          const __nv_bfloat16* __restrict__ Bh, const __nv_bfloat16* __restrict__ Bl, long sBb,
          float* __restrict__ Y, long sYb, const float* __restrict__ bias)
{
    constexpr int MI = 128/(WM*16), NI = BN/(WN*8);
    constexpr int KT = KTOT/32;
    constexpr int SS = 20480 + BN*160;
    extern __shared__ __align__(16) char smem[];
    const uint32_t sm0 = smem_u32(smem);
    const int tid=threadIdx.x, lane=tid&31, w=tid>>5;
    const int wm = w % WM, wn = w / WM;
    const int b=blockIdx.z, pt0=blockIdx.y*128, ch0=blockIdx.x*BN;

    const __nv_bfloat16* pAh = BNA ? nullptr : Ah + b*sAb + (long)pt0*KTOT;
    const __nv_bfloat16* pAl = BNA ? nullptr : Al + b*sAb + (long)pt0*KTOT;
    const float*         pAf = BNA ? Af + b*sAb + (long)pt0*KTOT : nullptr;
    const __nv_bfloat16* pBh = Bh + b*sBb + (long)ch0*KTOT;
    const __nv_bfloat16* pBl = Bl + b*sBb + (long)ch0*KTOT;
    float* Yb = Y + b*sYb;

    float acc[MI][NI][4];
#pragma unroll
    for(int i=0;i<MI;i++)
#pragma unroll
        for(int j=0;j<NI;j++){ acc[i][j][0]=0.f;acc[i][j][1]=0.f;acc[i][j][2]=0.f;acc[i][j][3]=0.f; }

    float4 av[4];
    auto loadA_regs = [&](int t){
        const int k0 = t*32;
#pragma unroll
        for (int i=0;i<4;i++){
            int idx = tid + i*256; int r = idx>>3, c = idx&7;
            av[i] = *(const float4*)(pAf + (long)r*KTOT + k0 + c*4);
        }
    };
    auto stsA = [&](int t){
        const uint32_t st = sm0 + (t&1)*SS;
        const int k0 = t*32;
#pragma unroll
        for (int i=0;i<4;i++){
            int idx = tid + i*256; int r = idx>>3, c = idx&7;
            int ch = k0 + c*4;
            float v0=fmaxf(fmaf(__ldg(bna+ch),  av[i].x,__ldg(bnc+ch)),  0.f);
            float v1=fmaxf(fmaf(__ldg(bna+ch+1),av[i].y,__ldg(bnc+ch+1)),0.f);
            float v2=fmaxf(fmaf(__ldg(bna+ch+2),av[i].z,__ldg(bnc+ch+2)),0.f);
            float v3=fmaxf(fmaf(__ldg(bna+ch+3),av[i].w,__ldg(bnc+ch+3)),0.f);
            __nv_bfloat16 h0=__float2bfloat16(v0),h1=__float2bfloat16(v1);
            __nv_bfloat16 h2=__float2bfloat16(v2),h3=__float2bfloat16(v3);
            uint32_t H0=pk(v0,v1), H1=pk(v2,v3);
            uint32_t L0=pk(v0-__bfloat162float(h0), v1-__bfloat162float(h1));
            uint32_t L1=pk(v2-__bfloat162float(h2), v3-__bfloat162float(h3));
            uint32_t ad = st + r*80 + c*8;
            STS64v(ad, H0, H1);
            STS64v(ad+10240, L0, L1);
        }
    };
    auto load_stage = [&](int t){
        const int k0 = t*32;
        const uint32_t st = sm0 + (t&1)*SS;
        if (!BNA){
#pragma unroll
            for (int i=0;i<2;i++){
                int idx = tid + i*256; int r = idx>>2, c = idx&3;
                CP16(st + r*80 + c*16,         pAh + (long)r*KTOT + k0 + c*8);
                CP16(st + 10240 + r*80 + c*16, pAl + (long)r*KTOT + k0 + c*8);
            }
        }
#pragma unroll
        for (int i=0;i<(BN*4+255)/256;i++){
            int idx = tid + i*256;
            if ((BN*4)%256==0 || idx<BN*4){
                int r = idx>>2, c = idx&3;
                CP16(st + 20480 + r*80 + c*16,         pBh + (long)r*KTOT + k0 + c*8);
                CP16(st + 20480 + BN*80 + r*80 + c*16, pBl + (long)r*KTOT + k0 + c*8);
            }
        }
        CPCOMMIT();
    };

    if (BNA) loadA_regs(0);
    load_stage(0);
    if (KT>1) load_stage(1);

    for (int t=0;t<KT;t++){
        if (BNA) stsA(t);
        if (t==KT-1) { CPWAIT0(); } else { CPWAIT1(); }
        __syncthreads();
        if (BNA && t+1<KT) loadA_regs(t+1);
        const uint32_t st = sm0 + (t&1)*SS;
#pragma unroll
        for (int ks=0;ks<2;ks++){
            const int kk=ks*16;
            uint32_t ah[MI][4], al[MI][4], bh[NI][2], bl[NI][2];
            const uint32_t koff = (kk + ((lane>>4)<<3))*2;
            uint32_t abase = st + (wm*MI*16 + (lane&15))*80 + koff;
#pragma unroll
            for (int mi=0;mi<MI;mi++){
                LDM4(ah[mi][0],ah[mi][1],ah[mi][2],ah[mi][3], abase + mi*16*80);
                LDM4(al[mi][0],al[mi][1],al[mi][2],al[mi][3], abase + mi*16*80 + 10240);
            }
            uint32_t bbase = st + 20480 + (wn*NI*8 + (lane&15))*80 + koff;
#pragma unroll
            for (int nj=0;nj<NI/2;nj++){
                uint32_t r0,r1,r2,r3;
                LDM4(r0,r1,r2,r3, bbase + nj*16*80);
                bh[2*nj][0]=r0; bh[2*nj][1]=r2; bh[2*nj+1][0]=r1; bh[2*nj+1][1]=r3;
                LDM4(r0,r1,r2,r3, bbase + nj*16*80 + BN*80);
                bl[2*nj][0]=r0; bl[2*nj][1]=r2; bl[2*nj+1][0]=r1; bl[2*nj+1][1]=r3;
            }
            // term-major: consecutive MMAs hit different accumulators (16-wide ILP);
            // per-accumulator order is still hh -> hl -> lh (bit-identical result)
#pragma unroll
            for (int mi=0;mi<MI;mi++)
#pragma unroll
                for (int ni=0;ni<NI;ni++)
                    MMA(acc[mi][ni], ah[mi], bh[ni]);
#pragma unroll
            for (int mi=0;mi<MI;mi++)
#pragma unroll
                for (int ni=0;ni<NI;ni++)
                    MMA(acc[mi][ni], ah[mi], bl[ni]);
#pragma unroll
            for (int mi=0;mi<MI;mi++)
#pragma unroll
                for (int ni=0;ni<NI;ni++)
                    MMA(acc[mi][ni], al[mi], bh[ni]);
        }
        __syncthreads();
        if (t+2 < KT) load_stage(t+2);
    }

    const int rbase = pt0 + wm*MI*16 + (lane>>2);
    const int cbase = ch0 + wn*NI*8 + (lane&3)*2;
#pragma unroll
    for (int mi=0;mi<MI;mi++)
#pragma unroll
        for (int ni=0;ni<NI;ni++){
            int r = rbase + mi*16, c = cbase + ni*8;
            float bv0 = BIAS ? bias[c] : 0.f, bv1 = BIAS ? bias[c+1] : 0.f;
            float* y0 = Yb + (long)r*CHTOT + c;
            y0[0]=acc[mi][ni][0]+bv0; y0[1]=acc[mi][ni][1]+bv1;
            float* y1 = y0 + 8*CHTOT;
            y1[0]=acc[mi][ni][2]+bv0; y1[1]=acc[mi][ni][3]+bv1;
        }
}

__global__ void w_split(const float* __restrict__ w1, const float* __restrict__ w2,
                        const float* __restrict__ w3, __nv_bfloat16* __restrict__ H,
                        __nv_bfloat16* __restrict__ L){
    int i=blockIdx.x*256+threadIdx.x; if(i>=802816) return;
    float v = (i<524288)? w1[i] : (i<786432? w2[i-524288] : w3[i-786432]);
    __nv_bfloat16 h=__float2bfloat16(v); H[i]=h; L[i]=__float2bfloat16(v-__bfloat162float(h));
}
__global__ void ft_split(const float* __restrict__ F, __nv_bfloat16* __restrict__ TH,
                         __nv_bfloat16* __restrict__ TL, __nv_bfloat16* __restrict__ DH,
                         __nv_bfloat16* __restrict__ DL, float* __restrict__ rn){
    __shared__ float t[32][33];
    __shared__ float part[8][32];
    int b=blockIdx.z, n0=blockIdx.x*32, d0=blockIdx.y*32, tx=threadIdx.x, ty=threadIdx.y;
    const float* Fb=F+((long)b<<22);
#pragma unroll
    for (int j=0;j<4;j++){
        float v=Fb[(long)(d0+ty*4+j)*4096+n0+tx];
        t[ty*4+j][tx]=v;
        long od=((long)(b*1024)+d0+ty*4+j)*4096+n0+tx;
        __nv_bfloat16 h=__float2bfloat16(v); DH[od]=h; DL[od]=__float2bfloat16(v-__bfloat162float(h));
    }
    __syncthreads();
    float s=0.f;
#pragma unroll
    for (int j=0;j<4;j++){
        float v=t[tx][ty*4+j];
        long o=((long)(b*4096)+n0+ty*4+j)*1024+d0+tx;
        __nv_bfloat16 h=__float2bfloat16(v); TH[o]=h; TL[o]=__float2bfloat16(v-__bfloat162float(h));
        float w2=t[ty*4+j][tx]; s=fmaf(w2,w2,s);
    }
    part[ty][tx]=s; __syncthreads();
    if (ty==0){
        float tot=0.f;
#pragma unroll
        for(int k=0;k<8;k++) tot+=part[k][tx];
        atomicAdd(&rn[(b<<12)+n0+tx], tot);
    }
}
__global__ void tr_split(const float* __restrict__ X, __nv_bfloat16* __restrict__ H,
                         __nv_bfloat16* __restrict__ L, int R){
    __shared__ float t[32][33];
    int b=blockIdx.z, r0=blockIdx.x*32, tx=threadIdx.x, ty=threadIdx.y;
#pragma unroll
    for (int j=0;j<4;j++)
        t[ty*4+j][tx]=X[((long)b*R+r0+ty*4+j)*32+tx];
    __syncthreads();
#pragma unroll
    for (int j=0;j<4;j++){
        float v=t[tx][ty*4+j];
        long o=((long)(b*32)+ty*4+j)*R + r0+tx;
        __nv_bfloat16 h=__float2bfloat16(v); H[o]=h; L[o]=__float2bfloat16(v-__bfloat162float(h));
    }
}
__global__ void bnT_partial(const float* __restrict__ Y, float* __restrict__ acc){
    int ch=threadIdx.x; long r0=(long)blockIdx.x*256;
    const float* p=Y+r0*512+ch;
    float s=0.f,s2=0.f;
    for (int r=0;r<256;r++){ float v=p[(long)r*512]; s+=v; s2=fmaf(v,v,s2); }
    atomicAdd(&acc[ch],s); atomicAdd(&acc[512+ch],s2);
}
__global__ void bnT_final(float* __restrict__ acc, const float* __restrict__ g,
                          const float* __restrict__ bb, float* __restrict__ aO, float* __restrict__ cO){
    int ch=threadIdx.x;
    float inv=1.f/32768.f, mean=acc[ch]*inv, var=acc[512+ch]*inv-mean*mean;
    float a=g[ch]*rsqrtf(var+1e-5f);
    aO[ch]=a; cO[ch]=bb[ch]-a*mean; acc[ch]=0.f; acc[512+ch]=0.f;
}
__global__ void reset_k(float* __restrict__ zt, long nz, float* __restrict__ o, long no,
                        int* __restrict__ fl){
    long i=(long)blockIdx.x*256+threadIdx.x;
    if (i<nz) zt[i]=0.f;
    else if (i<nz+no) o[i-nz]=0.f;
    if (i<4) fl[i]=0;
}

template<int BM,int BN,int BK,int TM,int TN,bool TA,int SPLITK>
__global__ void __launch_bounds__((BM/TM)*(BN/TN))
gemm_k(const float* __restrict__ A, long strideA, int lda,
       const float* __restrict__ B, long strideB,
       float* __restrict__ C, long strideC, int M, int Nn, int Kk,
       const float* __restrict__ bias, const float* __restrict__ bnS, const float* __restrict__ bnB)
{
    constexpr int THREADS=(BM/TM)*(BN/TN);
    const int bz=blockIdx.z, batch=bz/SPLITK, split=bz%SPLITK;
    const int kPer=Kk/SPLITK, kBeg=split*kPer, kEnd=kBeg+kPer;
    const float* Ap=A+(long)batch*strideA;
    const float* Bp=B+(long)batch*strideB;
    float* Cp=C+(long)batch*strideC;
    __shared__ __align__(16) float As[BK][BM+4];
    __shared__ __align__(16) float Bs[BK][BN+4];
    const int tid=threadIdx.x, tx=tid%(BN/TN), ty=tid/(BN/TN);
    const int m0=blockIdx.y*BM, n0=blockIdx.x*BN;
    float acc[TM][TN];
#pragma unroll
    for(int i=0;i<TM;i++)
#pragma unroll
        for(int j=0;j<TN;j++) acc[i][j]=0.f;
    for (int k0=kBeg;k0<kEnd;k0+=BK){
        if (!TA){ for(int i=tid;i<BM*BK;i+=THREADS){ int mm=i/BK,kk=i%BK; As[kk][mm]=Ap[(long)(m0+mm)*lda+(k0+kk)]; } }
        else    { for(int i=tid;i<BM*BK;i+=THREADS){ int kk=i/BM,mm=i%BM; As[kk][mm]=Ap[(long)(k0+kk)*lda+(m0+mm)]; } }
        for(int i=tid;i<BK*BN;i+=THREADS){
            int kk=i/BN,nn=i%BN;
            float v=Bp[(long)(k0+kk)*Nn+(n0+nn)];
            if (bnS){ int gk=k0+kk; v=fmaxf(fmaf(bnS[gk],v,bnB[gk]),0.f); }
            Bs[kk][nn]=v;
        }
        __syncthreads();
#pragma unroll
        for (int kk=0;kk<BK;kk++){
            float ra[TM],rb[TN];
#pragma unroll
            for(int h=0;h<TM/4;h++) *(float4*)(ra+4*h)=*(const float4*)(&As[kk][ty*TM+4*h]);
#pragma unroll
            for(int h=0;h<TN/4;h++) *(float4*)(rb+4*h)=*(const float4*)(&Bs[kk][tx*TN+4*h]);
#pragma unroll
            for(int i=0;i<TM;i++)
#pragma unroll
                for(int j=0;j<TN;j++) acc[i][j]=fmaf(ra[i],rb[j],acc[i][j]);
        }
        __syncthreads();
    }
#pragma unroll
    for (int i=0;i<TM;i++){
        int m=m0+ty*TM+i; float bv=bias?bias[m]:0.f;
#pragma unroll
        for (int j=0;j<TN;j++){
            int n=n0+tx*TN+j;
            if (SPLITK==1) Cp[(long)m*Nn+n]=acc[i][j]+bv;
            else atomicAdd(&Cp[(long)m*Nn+n],acc[i][j]+((split==0)?bv:0.f));
        }
    }
}

__global__ void bnproj_stats(const float* __restrict__ Y, const float* __restrict__ g,
                             const float* __restrict__ bb, float* __restrict__ aO,
                             float* __restrict__ cO, int Ch){
    int w=blockIdx.x*8+(threadIdx.x>>5), lane=threadIdx.x&31;
    if (w>=Ch) return;
    float s=0.f,s2=0.f;
#pragma unroll
    for(int b=0;b<BATCH;b++){ float v=Y[(((long)b*Ch+w)<<5)+lane]; s+=v; s2=fmaf(v,v,s2); }
#pragma unroll
    for(int o=16;o;o>>=1){ s+=__shfl_xor_sync(~0u,s,o); s2+=__shfl_xor_sync(~0u,s2,o); }
    if (lane==0){
        float inv=1.f/256.f, mean=s*inv, var=s2*inv-mean*mean;
        float a=g[w]*rsqrtf(var+1e-5f); aO[w]=a; cO[w]=bb[w]-a*mean;
    }
}
__global__ void bn2_stats(const float* __restrict__ Z, const float* __restrict__ g,
                          const float* __restrict__ bb, float* __restrict__ aO,
                          float* __restrict__ cO, int Ch){
    int ch=blockIdx.x*256+threadIdx.x; if(ch>=Ch) return;
    float s=0.f;
#pragma unroll
    for(int b=0;b<BATCH;b++) s+=Z[(long)b*Ch+ch];
    float mean=s*0.125f, v=0.f;
#pragma unroll
    for(int b=0;b<BATCH;b++){ float d=Z[(long)b*Ch+ch]-mean; v=fmaf(d,d,v); }
    v*=0.125f;
    float a=g[ch]*rsqrtf(v+1e-5f); aO[ch]=a; cO[ch]=bb[ch]-a*mean;
}
__global__ void softmax_pi(const float* __restrict__ ls, float* __restrict__ sT,
                           float* __restrict__ pi){
    __shared__ float spi[32];
    if (threadIdx.x<32) spi[threadIdx.x]=0.f;
    __syncthreads();
    int idx=blockIdx.x*256+threadIdx.x, pt=idx>>5, lane=idx&31;
    float x=ls[((long)pt<<5)+lane], m=x;
#pragma unroll
    for(int o=16;o;o>>=1) m=fmaxf(m,__shfl_xor_sync(~0u,m,o));
    float e=__expf(x-m), s=e;
#pragma unroll
    for(int o=16;o;o>>=1) s+=__shfl_xor_sync(~0u,s,o);
    float pr=e/s;
    sT[((long)pt<<5)+lane]=pr;
    atomicAdd(&spi[lane],pr);
    __syncthreads();
    if (threadIdx.x<32) atomicAdd(&pi[((blockIdx.x>>9)<<5)+threadIdx.x],spi[threadIdx.x]);
}
__global__ void vlad_fin(float* __restrict__ vlad, const float* __restrict__ pi,
                         float* __restrict__ pool){
    int b=blockIdx.y, d=blockIdx.x*256+threadIdx.x;
    __shared__ float ip[32];
    if (threadIdx.x<32) ip[threadIdx.x]=1.f/fmaxf(pi[(b<<5)+threadIdx.x],1e-4f);
    __syncthreads();
    float4* vp=(float4*)(vlad+(((long)((b<<10)+d))<<5));
    float mx=-CUDART_INF_F;
#pragma unroll
    for(int q=0;q<8;q++){
        float4 v=vp[q];
        v.x*=ip[4*q]; v.y*=ip[4*q+1]; v.z*=ip[4*q+2]; v.w*=ip[4*q+3];
        mx=fmaxf(mx,fmaxf(fmaxf(v.x,v.y),fmaxf(v.z,v.w)));
        vp[q]=v;
    }
    pool[(b<<10)+d]=mx;
}
__global__ void rmu_k(const float* __restrict__ vlad, float* __restrict__ rmu){
    int b=blockIdx.x, k=threadIdx.x>>5, lane=threadIdx.x&31;
    float s=0.f;
    for(int d=lane;d<DIM;d+=32){ float x=vlad[(((long)((b<<10)+d))<<5)+k]; s=fmaf(x,x,s); }
#pragma unroll
    for(int o=16;o;o>>=1) s+=__shfl_xor_sync(~0u,s,o);
    if(lane==0) rmu[(b<<5)+k]=1.f/fmaxf(sqrtf(s),1e-12f);
}
__global__ void cost_fin(float* __restrict__ cost, float* __restrict__ costT,
                         const float* __restrict__ rnacc, const float* __restrict__ rmu){
    int b=blockIdx.y, n=blockIdx.x*256+threadIdx.x;
    __shared__ float rm[32];
    if (threadIdx.x<32) rm[threadIdx.x]=rmu[(b<<5)+threadIdx.x];
    __syncthreads();
    float r2=2.f/fmaxf(sqrtf(rnacc[(b<<12)+n]),1e-12f);
    float4* cp=(float4*)(cost+(((long)((b<<12)+n))<<5));
    float val[32];
#pragma unroll
    for(int q=0;q<8;q++){
        float4 v=cp[q];
        val[4*q]=2.f-v.x*r2*rm[4*q]; val[4*q+1]=2.f-v.y*r2*rm[4*q+1];
        val[4*q+2]=2.f-v.z*r2*rm[4*q+2]; val[4*q+3]=2.f-v.w*r2*rm[4*q+3];
        cp[q]=make_float4(val[4*q],val[4*q+1],val[4*q+2],val[4*q+3]);
    }
#pragma unroll
    for(int k=0;k<32;k++) costT[(((long)((b<<5)+k))<<12)+n]=val[k];
}

__global__ void __launch_bounds__(128)
sinkhorn_fused(const float* __restrict__ cost, const float* __restrict__ costT,
               const float* __restrict__ sT, float* __restrict__ u,
               float* __restrict__ v, float* __restrict__ dsum,
               unsigned* __restrict__ bar, float* __restrict__ out0)
{
    const int tid=threadIdx.x, bid=blockIdx.x;
    const int p = bid*128+tid;
    const int b = p>>12;
    __shared__ float red[128];
    __shared__ float sm[128], ssx[128];
    for (int it=0; it<25; ++it){
        {
            const float* vb = v + (b<<5);
            const float4* cp=(const float4*)(cost+((long)p<<5));
            float t[32];
#pragma unroll
            for(int q=0;q<8;q++){
                float4 c4=cp[q];
                t[4*q]=vb[4*q]-c4.x; t[4*q+1]=vb[4*q+1]-c4.y;
                t[4*q+2]=vb[4*q+2]-c4.z; t[4*q+3]=vb[4*q+3]-c4.w;
            }
            float m=t[0];
#pragma unroll
            for(int k=1;k<32;k++) m=fmaxf(m,t[k]);
            float s=0.f;
#pragma unroll
            for(int k=0;k<32;k++) s+=__expf((t[k]-m)*INV_EPS);
            float un=EPSS*LOGP_C-m-EPSS*__logf(s);
            float dl=fabsf(un-u[p]); u[p]=un;
            red[tid]=dl; __syncthreads();
            for(int st=64;st;st>>=1){ if(tid<st) red[tid]+=red[tid+st]; __syncthreads(); }
            if (tid==0) atomicAdd(&dsum[it],red[0]);
        }
        gbar(bar,bar+1,256u);
        {
            const float* row=costT+((long)bid<<12);
            const float* ub=u+((bid>>5)<<12);
            float mm=-CUDART_INF_F, ss=0.f;
            for(int i=tid;i<NPTS;i+=128){
                float x=ub[i]-row[i];
                if (x>mm){ ss=ss*__expf((mm-x)*INV_EPS)+1.f; mm=x; } else ss+=__expf((x-mm)*INV_EPS);
            }
            sm[tid]=mm; ssx[tid]=ss; __syncthreads();
            for(int st=64;st;st>>=1){
                if(tid<st){
                    float m1=sm[tid],s1=ssx[tid],m2=sm[tid+st],s2=ssx[tid+st];
                    float M=fmaxf(m1,m2);
                    ssx[tid]=s1*__expf((m1-M)*INV_EPS)+s2*__expf((m2-M)*INV_EPS);
                    sm[tid]=M;
                }
                __syncthreads();
            }
            if (tid==0){
                float vn=EPSS*LOGQ_C-sm[0]-EPSS*__logf(ssx[0]);
                atomicAdd(&dsum[it],fabsf(vn-v[bid]));
                v[bid]=vn;
            }
        }
        gbar(bar,bar+1,256u);
        float dd = *((volatile float*)&dsum[it]);
        if (dd*0.125f < 1e-3f) break;
    }
    {
        const float* vb = v + (b<<5);
        float uu = u[p];
        const float4* cp=(const float4*)(cost+((long)p<<5));
        const float4* sp=(const float4*)(sT+((long)p<<5));
        float acc=0.f;
#pragma unroll
        for(int q=0;q<8;q++){
            float4 c4=cp[q]; float4 s4=sp[q];
            acc+=__expf((uu+vb[4*q]-c4.x)*INV_EPS)*__logf(fmaxf(s4.x,1e-38f));
            acc+=__expf((uu+vb[4*q+1]-c4.y)*INV_EPS)*__logf(fmaxf(s4.y,1e-38f));
            acc+=__expf((uu+vb[4*q+2]-c4.z)*INV_EPS)*__logf(fmaxf(s4.z,1e-38f));
            acc+=__expf((uu+vb[4*q+3]-c4.w)*INV_EPS)*__logf(fmaxf(s4.w,1e-38f));
        }
        red[tid]=acc; __syncthreads();
        for(int st=64;st;st>>=1){ if(tid<st) red[tid]+=red[tid+st]; __syncthreads(); }
        if (tid==0) atomicAdd(out0,red[0]*(-0.125f));
    }
}

template<bool ACT>
__global__ void fc_k(const float* __restrict__ X, const float* __restrict__ W,
                     float* __restrict__ C, int O, int Kin, const float* __restrict__ bias,
                     const float* __restrict__ a, const float* __restrict__ c){
    int gw=(blockIdx.x*256+threadIdx.x)>>5, lane=threadIdx.x&31;
    int b=gw/O, o=gw-b*O;
    const float* x=X+(long)b*Kin;
    const float* wr=W+(long)o*Kin;
    float s=0.f;
    for(int k=lane;k<Kin;k+=32){
        float xv=x[k];
        if (ACT) xv=fmaxf(fmaf(a[k],xv,c[k]),0.f);
        s=fmaf(xv,wr[k],s);
    }
#pragma unroll
    for(int o2=16;o2;o2>>=1) s+=__shfl_xor_sync(~0u,s,o2);
    if(lane==0) C[(long)b*O+o]=s+(bias?bias[o]:0.f);
}

extern "C" void kernel_launch(void* const* d_in, const int* in_sizes, int n_in,
                              void* d_out, int out_size)
{
    const float *F=(const float*)d_in[0];
    const float *cw1=(const float*)d_in[1], *cg1=(const float*)d_in[3], *ct1=(const float*)d_in[4];
    const float *cw2=(const float*)d_in[5], *cg2=(const float*)d_in[7], *ct2=(const float*)d_in[8];
    const float *cw3=(const float*)d_in[9], *cb3=(const float*)d_in[10];
    const float *pw1=(const float*)d_in[11], *pg1=(const float*)d_in[13], *pt1=(const float*)d_in[14];
    const float *pw2=(const float*)d_in[15], *pg2=(const float*)d_in[17], *pt2=(const float*)d_in[18];
    const float *pw3=(const float*)d_in[19], *pb3=(const float*)d_in[20];
    const float *mw1=(const float*)d_in[21], *mg1=(const float*)d_in[23], *mt1=(const float*)d_in[24];
    const float *mw2=(const float*)d_in[25], *mg2=(const float*)d_in[27], *mt2=(const float*)d_in[28];
    const float *mw3=(const float*)d_in[29], *mb3=(const float*)d_in[30];
    float* out=(float*)d_out;

    static float* S=nullptr; static int* FL=nullptr;
    static __nv_bfloat16 *FTh,*FTl,*Fh,*Fl,*Wh,*Wl,*SCh,*SCl,*VTh,*VTl;
    static float *YT,*YT2;
    if (!S){
        cudaGetSymbolAddress((void**)&S,d_scratch);
        cudaGetSymbolAddress((void**)&FL,d_flags);
        cudaGetSymbolAddress((void**)&FTh,d_FTh); cudaGetSymbolAddress((void**)&FTl,d_FTl);
        cudaGetSymbolAddress((void**)&Fh,d_Fh);   cudaGetSymbolAddress((void**)&Fl,d_Fl);
        cudaGetSymbolAddress((void**)&Wh,d_Wh);   cudaGetSymbolAddress((void**)&Wl,d_Wl);
        cudaGetSymbolAddress((void**)&SCh,d_SCh); cudaGetSymbolAddress((void**)&SCl,d_SCl);
        cudaGetSymbolAddress((void**)&VTh,d_VTh); cudaGetSymbolAddress((void**)&VTl,d_VTl);
        cudaGetSymbolAddress((void**)&YT,d_YT);   cudaGetSymbolAddress((void**)&YT2,d_YT2);
        cudaFuncSetAttribute(hmma_gemm<1024,128,2,4,512,false,false>,cudaFuncAttributeMaxDynamicSharedMemorySize,81920);
        cudaFuncSetAttribute(hmma_gemm<512,128,2,4,512,false,true>,cudaFuncAttributeMaxDynamicSharedMemorySize,81920);
        cudaFuncSetAttribute(hmma_gemm<512,32,8,1,32,true,true>,cudaFuncAttributeMaxDynamicSharedMemorySize,51200);
        cudaFuncSetAttribute(hmma_gemm<4096,32,8,1,32,false,false>,cudaFuncAttributeMaxDynamicSharedMemorySize,51200);
        cudaFuncSetAttribute(hmma_gemm<1024,32,8,1,32,false,false>,cudaFuncAttributeMaxDynamicSharedMemorySize,51200);
    }
    float *LS=S+OFF_LS,*ST=S+OFF_ST,*COST=S+OFF_COST,*COSTT=S+OFF_COSTT;
    float *RN=S+OFF_RN,*POOL=S+OFF_POOL,*P1=S+OFF_P1,*P2=S+OFF_P2;
    float *Z1=S+OFF_Z1,*Z2=S+OFF_Z2,*BNC=S+OFF_BN;
    float *VLAD=S+OFF_VLAD,*PI=S+OFF_PI,*U=S+OFF_U,*V=S+OFF_V,*RMU=S+OFF_RMU;
    float *ACC=S+OFF_ACC,*DS=S+OFF_DSUM;
    float *a1=BNC,*c1=BNC+512,*a2=BNC+1024,*c2=BNC+1536;
    float *ap1=BNC+2048,*cp1=BNC+2560,*ap2=BNC+3072,*cp2=BNC+3584;
    float *am1=BNC+4096,*cm1=BNC+4608,*am2=BNC+5120,*cm2=BNC+5632;

    reset_k<<<(int)((ZTAIL+32897+255)/256),256>>>(S+OFF_VLAD,ZTAIL,out,32897,FL);
    w_split<<<3137,256>>>(cw1,cw2,cw3,Wh,Wl);
    ft_split<<<dim3(128,32,8),dim3(32,8)>>>(F,FTh,FTl,Fh,Fl,RN);

    // score head on HMMA (bf16x3); BN-relu+split fused into A-load of G2/G3
    hmma_gemm<1024,128,2,4,512,false,false><<<dim3(4,32,8),256,81920>>>(
        FTh,FTl,4194304L, nullptr,nullptr,nullptr, Wh,Wl,0L, YT,2097152L,nullptr);
    bnT_partial<<<128,512>>>(YT,ACC);
    bnT_final<<<1,512>>>(ACC,cg1,ct1,a1,c1);
    hmma_gemm<512,128,2,4,512,false,true><<<dim3(4,32,8),256,81920>>>(
        nullptr,nullptr,2097152L, YT,a1,c1, Wh+524288,Wl+524288,0L, YT2,2097152L,nullptr);
    bnT_partial<<<128,512>>>(YT2,ACC);
    bnT_final<<<1,512>>>(ACC,cg2,ct2,a2,c2);
    hmma_gemm<512,32,8,1,32,true,true><<<dim3(1,32,8),256,51200>>>(
        nullptr,nullptr,2097152L, YT2,a2,c2, Wh+786432,Wl+786432,0L, LS,131072L,cb3);

    softmax_pi<<<4096,256>>>(LS,ST,PI);
    tr_split<<<dim3(128,1,8),dim3(32,8)>>>(ST,SCh,SCl,4096);
    hmma_gemm<4096,32,8,1,32,false,false><<<dim3(1,8,8),256,51200>>>(
        Fh,Fl,4194304L, nullptr,nullptr,nullptr, SCh,SCl,131072L, VLAD,32768L,nullptr);
    vlad_fin<<<dim3(4,8),256>>>(VLAD,PI,POOL);
    rmu_k<<<8,1024>>>(VLAD,RMU);
    tr_split<<<dim3(32,1,8),dim3(32,8)>>>(VLAD,VTh,VTl,1024);
    hmma_gemm<1024,32,8,1,32,false,false><<<dim3(1,32,8),256,51200>>>(
        FTh,FTl,4194304L, nullptr,nullptr,nullptr, VTh,VTl,32768L, COST,131072L,nullptr);
    cost_fin<<<dim3(16,8),256>>>(COST,COSTT,RN,RMU);

    sinkhorn_fused<<<256,128>>>(COST,COSTT,ST,U,V,DS,(unsigned*)(FL+2),out);

    gemm_k<128,32,16,8,4,false,8><<<dim3(1,4,64),128>>>(
        pw1,0,DIM, VLAD,(long)DIM*KCL, P1,(long)HID*KCL, HID,KCL,DIM, nullptr,nullptr,nullptr);
    bnproj_stats<<<64,256>>>(P1,pg1,pt1,ap1,cp1,HID);
    gemm_k<128,32,16,8,4,false,8><<<dim3(1,4,64),128>>>(
        pw2,0,HID, P1,(long)HID*KCL, P2,(long)HID*KCL, HID,KCL,HID, nullptr,ap1,cp1);
    bnproj_stats<<<64,256>>>(P2,pg2,pt2,ap2,cp2,HID);
    gemm_k<64,32,16,4,4,false,8><<<dim3(1,2,64),128>>>(
        pw3,0,HID, P2,(long)HID*KCL, out+1,(long)PRJ*KCL, PRJ,KCL,HID, pb3,ap2,cp2);

    fc_k<false><<<512,256>>>(POOL,mw1,Z1,HID,DIM,nullptr,nullptr,nullptr);
    bn2_stats<<<2,256>>>(Z1,mg1,mt1,am1,cm1,HID);
    fc_k<true ><<<512,256>>>(Z1,mw2,Z2,HID,HID,nullptr,am1,cm1);
    bn2_stats<<<2,256>>>(Z2,mg2,mt2,am2,cm2,HID);
    fc_k<true ><<<128,256>>>(Z2,mw3,out+1+32768,PRJ,HID,mb3,am2,cm2);
}

// round 16
// speedup vs baseline: 1.0408x; 1.0010x over previous
#include <cuda_runtime.h>
#include <cuda_bf16.h>
#include <math_constants.h>
#include <stdint.h>

#define BATCH 8
#define DIM 1024
#define NPTS 4096
#define KCL 32
#define HID 512
#define PRJ 128
#define EPSS 1e-3f
#define INV_EPS 1000.0f
#define LOGP_C (-8.3177252f)
#define LOGQ_C (-3.4657356f)

constexpr long OFF_LS=0, OFF_ST=1048576, OFF_COST=2097152, OFF_COSTT=3145728;
constexpr long OFF_POOL=4194304, OFF_Z1=4202496, OFF_Z2=4206592, OFF_BN=4210688;
constexpr long OFF_VLAD=4216832, OFF_PI=4478976, OFF_U=4479232, OFF_V=4512000;
constexpr long OFF_RMU=4512256, OFF_ACC=4512512, OFF_DSUM=4513536, OFF_RN=4513568;
constexpr long OFF_P1=4546336, OFF_P2=4677408;
constexpr long SCRATCH_SZ=4808480;
constexpr long ZTAIL=SCRATCH_SZ-OFF_VLAD;

static __device__ float d_scratch[SCRATCH_SZ];
static __device__ int   d_flags[4];
static __device__ __nv_bfloat16 d_FTh[33554432], d_FTl[33554432];
static __device__ __nv_bfloat16 d_Fh[33554432],  d_Fl[33554432];
static __device__ __nv_bfloat16 d_Wh[802816],    d_Wl[802816];
static __device__ __nv_bfloat16 d_SCh[1048576],  d_SCl[1048576];
static __device__ __nv_bfloat16 d_VTh[262144],   d_VTl[262144];
static __device__ float d_YT[16777216];
static __device__ float d_YT2[16777216];

__device__ __forceinline__ uint32_t smem_u32(const void* p){
    uint32_t a; asm("{ .reg .u64 t; cvta.to.shared.u64 t,%1; cvt.u32.u64 %0,t; }":"=r"(a):"l"(p)); return a;
}
#define CP16(dst,src) asm volatile("cp.async.cg.shared.global [%0],[%1],16;"::"r"(dst),"l"(src):"memory")
#define CPCOMMIT() asm volatile("cp.async.commit_group;":::"memory")
#define CPWAIT1() asm volatile("cp.async.wait_group 1;":::"memory")
#define CPWAIT0() asm volatile("cp.async.wait_group 0;":::"memory")
#define LDM4(r0,r1,r2,r3,ad) asm volatile("ldmatrix.sync.aligned.m8n8.x4.shared.b16 {%0,%1,%2,%3},[%4];":"=r"(r0),"=r"(r1),"=r"(r2),"=r"(r3):"r"(ad))
#define STS64v(a,r0,r1) asm volatile("st.shared.v2.b32 [%0],{%1,%2};"::"r"(a),"r"(r0),"r"(r1):"memory")
#define MMA(d,a,b) asm volatile("mma.sync.aligned.m16n8k16.row.col.f32.bf16.bf16.f32 {%0,%1,%2,%3},{%4,%5,%6,%7},{%8,%9},{%0,%1,%2,%3};" \
  :"+f"((d)[0]),"+f"((d)[1]),"+f"((d)[2]),"+f"((d)[3]) \
  :"r"((a)[0]),"r"((a)[1]),"r"((a)[2]),"r"((a)[3]),"r"((b)[0]),"r"((b)[1]))

__device__ __forceinline__ void gbar(unsigned* cnt, unsigned* gen, unsigned nb){
    __syncthreads();
    if (threadIdx.x==0){
        unsigned g = *((volatile unsigned*)gen);
        __threadfence();
        if (atomicAdd(cnt,1u)==nb-1u){ *cnt=0u; __threadfence(); atomicAdd(gen,1u); }
        else { while (*((volatile unsigned*)gen)==g) {} }
    }
    __syncthreads();
}
__device__ __forceinline__ uint32_t pk(float v0, float v1){
    __nv_bfloat162 h(__float2bfloat16(v0),__float2bfloat16(v1));
    return *(uint32_t*)&h;
}

// Y[row,ch] = sum_k A[row,k]*B[ch,k], bf16x3 split, fp32 acc.
// BNA: A is fp32 Af with relu(bna*x+bnc) + h/l split done in the load path.
template<int KTOT,int BN,int WM,int WN,int CHTOT,bool BIAS,bool BNA>
__global__ void __launch_bounds__(256,1)
hmma_gemm(const __nv_bfloat16* __restrict__ Ah, const __nv_bfloat16* __restrict__ Al, long sAb,
          const float* __restrict__ Af, const float* __restrict__ bna, const float* __restrict__ bnc,
          const __nv_bfloat16* __restrict__ Bh, const __nv_bfloat16* __restrict__ Bl, long sBb,
          float* __restrict__ Y, long sYb, const float* __restrict__ bias)
{
    constexpr int MI = 128/(WM*16), NI = BN/(WN*8);
    constexpr int KT = KTOT/32;
    constexpr int SS = 20480 + BN*160;
    extern __shared__ __align__(16) char smem[];
    const uint32_t sm0 = smem_u32(smem);
    const int tid=threadIdx.x, lane=tid&31, w=tid>>5;
    const int wm = w % WM, wn = w / WM;
    const int b=blockIdx.z, pt0=blockIdx.y*128, ch0=blockIdx.x*BN;

    const __nv_bfloat16* pAh = BNA ? nullptr : Ah + b*sAb + (long)pt0*KTOT;
    const __nv_bfloat16* pAl = BNA ? nullptr : Al + b*sAb + (long)pt0*KTOT;
    const float*         pAf = BNA ? Af + b*sAb + (long)pt0*KTOT : nullptr;
    const __nv_bfloat16* pBh = Bh + b*sBb + (long)ch0*KTOT;
    const __nv_bfloat16* pBl = Bl + b*sBb + (long)ch0*KTOT;
    float* Yb = Y + b*sYb;

    float acc[MI][NI][4];
#pragma unroll
    for(int i=0;i<MI;i++)
#pragma unroll
        for(int j=0;j<NI;j++){ acc[i][j][0]=0.f;acc[i][j][1]=0.f;acc[i][j][2]=0.f;acc[i][j][3]=0.f; }

    float4 av[4];
    auto loadA_regs = [&](int t){
        const int k0 = t*32;
#pragma unroll
        for (int i=0;i<4;i++){
            int idx = tid + i*256; int r = idx>>3, c = idx&7;
            av[i] = *(const float4*)(pAf + (long)r*KTOT + k0 + c*4);
        }
    };
    auto stsA = [&](int t){
        const uint32_t st = sm0 + (t&1)*SS;
        const int k0 = t*32;
#pragma unroll
        for (int i=0;i<4;i++){
            int idx = tid + i*256; int r = idx>>3, c = idx&7;
            int ch = k0 + c*4;
            float v0=fmaxf(fmaf(__ldg(bna+ch),  av[i].x,__ldg(bnc+ch)),  0.f);
            float v1=fmaxf(fmaf(__ldg(bna+ch+1),av[i].y,__ldg(bnc+ch+1)),0.f);
            float v2=fmaxf(fmaf(__ldg(bna+ch+2),av[i].z,__ldg(bnc+ch+2)),0.f);
            float v3=fmaxf(fmaf(__ldg(bna+ch+3),av[i].w,__ldg(bnc+ch+3)),0.f);
            __nv_bfloat16 h0=__float2bfloat16(v0),h1=__float2bfloat16(v1);
            __nv_bfloat16 h2=__float2bfloat16(v2),h3=__float2bfloat16(v3);
            uint32_t H0=pk(v0,v1), H1=pk(v2,v3);
            uint32_t L0=pk(v0-__bfloat162float(h0), v1-__bfloat162float(h1));
            uint32_t L1=pk(v2-__bfloat162float(h2), v3-__bfloat162float(h3));
            uint32_t ad = st + r*80 + c*8;
            STS64v(ad, H0, H1);
            STS64v(ad+10240, L0, L1);
        }
    };
    auto load_stage = [&](int t){
        const int k0 = t*32;
        const uint32_t st = sm0 + (t&1)*SS;
        if (!BNA){
#pragma unroll
            for (int i=0;i<2;i++){
                int idx = tid + i*256; int r = idx>>2, c = idx&3;
                CP16(st + r*80 + c*16,         pAh + (long)r*KTOT + k0 + c*8);
                CP16(st + 10240 + r*80 + c*16, pAl + (long)r*KTOT + k0 + c*8);
            }
        }
#pragma unroll
        for (int i=0;i<(BN*4+255)/256;i++){
            int idx = tid + i*256;
            if ((BN*4)%256==0 || idx<BN*4){
                int r = idx>>2, c = idx&3;
                CP16(st + 20480 + r*80 + c*16,         pBh + (long)r*KTOT + k0 + c*8);
                CP16(st + 20480 + BN*80 + r*80 + c*16, pBl + (long)r*KTOT + k0 + c*8);
            }
        }
        CPCOMMIT();
    };

    if (BNA) loadA_regs(0);
    load_stage(0);
    if (KT>1) load_stage(1);

    for (int t=0;t<KT;t++){
        if (BNA) stsA(t);
        if (t==KT-1) { CPWAIT0(); } else { CPWAIT1(); }
        __syncthreads();
        if (BNA && t+1<KT) loadA_regs(t+1);
        const uint32_t st = sm0 + (t&1)*SS;
#pragma unroll
        for (int ks=0;ks<2;ks++){
            const int kk=ks*16;
            uint32_t ah[MI][4], al[MI][4], bh[NI][2], bl[NI][2];
            const uint32_t koff = (kk + ((lane>>4)<<3))*2;
            uint32_t abase = st + (wm*MI*16 + (lane&15))*80 + koff;
#pragma unroll
            for (int mi=0;mi<MI;mi++){
                LDM4(ah[mi][0],ah[mi][1],ah[mi][2],ah[mi][3], abase + mi*16*80);
                LDM4(al[mi][0],al[mi][1],al[mi][2],al[mi][3], abase + mi*16*80 + 10240);
            }
            uint32_t bbase = st + 20480 + (wn*NI*8 + (lane&15))*80 + koff;
#pragma unroll
            for (int nj=0;nj<NI/2;nj++){
                uint32_t r0,r1,r2,r3;
                LDM4(r0,r1,r2,r3, bbase + nj*16*80);
                bh[2*nj][0]=r0; bh[2*nj][1]=r2; bh[2*nj+1][0]=r1; bh[2*nj+1][1]=r3;
                LDM4(r0,r1,r2,r3, bbase + nj*16*80 + BN*80);
                bl[2*nj][0]=r0; bl[2*nj][1]=r2; bl[2*nj+1][0]=r1; bl[2*nj+1][1]=r3;
            }
#pragma unroll
            for (int mi=0;mi<MI;mi++)
#pragma unroll
                for (int ni=0;ni<NI;ni++){
                    MMA(acc[mi][ni], ah[mi], bh[ni]);
                    MMA(acc[mi][ni], ah[mi], bl[ni]);
                    MMA(acc[mi][ni], al[mi], bh[ni]);
                }
        }
        __syncthreads();
        if (t+2 < KT) load_stage(t+2);
    }

    const int rbase = pt0 + wm*MI*16 + (lane>>2);
    const int cbase = ch0 + wn*NI*8 + (lane&3)*2;
#pragma unroll
    for (int mi=0;mi<MI;mi++)
#pragma unroll
        for (int ni=0;ni<NI;ni++){
            int r = rbase + mi*16, c = cbase + ni*8;
            float bv0 = BIAS ? bias[c] : 0.f, bv1 = BIAS ? bias[c+1] : 0.f;
            float* y0 = Yb + (long)r*CHTOT + c;
            y0[0]=acc[mi][ni][0]+bv0; y0[1]=acc[mi][ni][1]+bv1;
            float* y1 = y0 + 8*CHTOT;
            y1[0]=acc[mi][ni][2]+bv0; y1[1]=acc[mi][ni][3]+bv1;
        }
}

__global__ void w_split(const float* __restrict__ w1, const float* __restrict__ w2,
                        const float* __restrict__ w3, __nv_bfloat16* __restrict__ H,
                        __nv_bfloat16* __restrict__ L){
    int i=blockIdx.x*256+threadIdx.x; if(i>=802816) return;
    float v = (i<524288)? w1[i] : (i<786432? w2[i-524288] : w3[i-786432]);
    __nv_bfloat16 h=__float2bfloat16(v); H[i]=h; L[i]=__float2bfloat16(v-__bfloat162float(h));
}
__global__ void ft_split(const float* __restrict__ F, __nv_bfloat16* __restrict__ TH,
                         __nv_bfloat16* __restrict__ TL, __nv_bfloat16* __restrict__ DH,
                         __nv_bfloat16* __restrict__ DL, float* __restrict__ rn){
    __shared__ float t[32][33];
    __shared__ float part[8][32];
    int b=blockIdx.z, n0=blockIdx.x*32, d0=blockIdx.y*32, tx=threadIdx.x, ty=threadIdx.y;
    const float* Fb=F+((long)b<<22);
#pragma unroll
    for (int j=0;j<4;j++){
        float v=Fb[(long)(d0+ty*4+j)*4096+n0+tx];
        t[ty*4+j][tx]=v;
        long od=((long)(b*1024)+d0+ty*4+j)*4096+n0+tx;
        __nv_bfloat16 h=__float2bfloat16(v); DH[od]=h; DL[od]=__float2bfloat16(v-__bfloat162float(h));
    }
    __syncthreads();
    float s=0.f;
#pragma unroll
    for (int j=0;j<4;j++){
        float v=t[tx][ty*4+j];
        long o=((long)(b*4096)+n0+ty*4+j)*1024+d0+tx;
        __nv_bfloat16 h=__float2bfloat16(v); TH[o]=h; TL[o]=__float2bfloat16(v-__bfloat162float(h));
        float w2=t[ty*4+j][tx]; s=fmaf(w2,w2,s);
    }
    part[ty][tx]=s; __syncthreads();
    if (ty==0){
        float tot=0.f;
#pragma unroll
        for(int k=0;k<8;k++) tot+=part[k][tx];
        atomicAdd(&rn[(b<<12)+n0+tx], tot);
    }
}
__global__ void tr_split(const float* __restrict__ X, __nv_bfloat16* __restrict__ H,
                         __nv_bfloat16* __restrict__ L, int R){
    __shared__ float t[32][33];
    int b=blockIdx.z, r0=blockIdx.x*32, tx=threadIdx.x, ty=threadIdx.y;
#pragma unroll
    for (int j=0;j<4;j++)
        t[ty*4+j][tx]=X[((long)b*R+r0+ty*4+j)*32+tx];
    __syncthreads();
#pragma unroll
    for (int j=0;j<4;j++){
        float v=t[tx][ty*4+j];
        long o=((long)(b*32)+ty*4+j)*R + r0+tx;
        __nv_bfloat16 h=__float2bfloat16(v); H[o]=h; L[o]=__float2bfloat16(v-__bfloat162float(h));
    }
}
__global__ void bnT_partial(const float* __restrict__ Y, float* __restrict__ acc){
    int ch=threadIdx.x; long r0=(long)blockIdx.x*256;
    const float* p=Y+r0*512+ch;
    float s=0.f,s2=0.f;
    for (int r=0;r<256;r++){ float v=p[(long)r*512]; s+=v; s2=fmaf(v,v,s2); }
    atomicAdd(&acc[ch],s); atomicAdd(&acc[512+ch],s2);
}
__global__ void bnT_final(float* __restrict__ acc, const float* __restrict__ g,
                          const float* __restrict__ bb, float* __restrict__ aO, float* __restrict__ cO){
    int ch=threadIdx.x;
    float inv=1.f/32768.f, mean=acc[ch]*inv, var=acc[512+ch]*inv-mean*mean;
    float a=g[ch]*rsqrtf(var+1e-5f);
    aO[ch]=a; cO[ch]=bb[ch]-a*mean; acc[ch]=0.f; acc[512+ch]=0.f;
}
__global__ void zero_k(float* __restrict__ p, long n){
    long i=(long)blockIdx.x*256+threadIdx.x; if(i<n) p[i]=0.f;
}
__global__ void init_k(int* f){ if(threadIdx.x<4) f[threadIdx.x]=0; }

template<int BM,int BN,int BK,int TM,int TN,bool TA,int SPLITK>
__global__ void __launch_bounds__((BM/TM)*(BN/TN))
gemm_k(const float* __restrict__ A, long strideA, int lda,
       const float* __restrict__ B, long strideB,
       float* __restrict__ C, long strideC, int M, int Nn, int Kk,
       const float* __restrict__ bias, const float* __restrict__ bnS, const float* __restrict__ bnB)
{
    constexpr int THREADS=(BM/TM)*(BN/TN);
    const int bz=blockIdx.z, batch=bz/SPLITK, split=bz%SPLITK;
    const int kPer=Kk/SPLITK, kBeg=split*kPer, kEnd=kBeg+kPer;
    const float* Ap=A+(long)batch*strideA;
    const float* Bp=B+(long)batch*strideB;
    float* Cp=C+(long)batch*strideC;
    __shared__ __align__(16) float As[BK][BM+4];
    __shared__ __align__(16) float Bs[BK][BN+4];
    const int tid=threadIdx.x, tx=tid%(BN/TN), ty=tid/(BN/TN);
    const int m0=blockIdx.y*BM, n0=blockIdx.x*BN;
    float acc[TM][TN];
#pragma unroll
    for(int i=0;i<TM;i++)
#pragma unroll
        for(int j=0;j<TN;j++) acc[i][j]=0.f;
    for (int k0=kBeg;k0<kEnd;k0+=BK){
        if (!TA){ for(int i=tid;i<BM*BK;i+=THREADS){ int mm=i/BK,kk=i%BK; As[kk][mm]=Ap[(long)(m0+mm)*lda+(k0+kk)]; } }
        else    { for(int i=tid;i<BM*BK;i+=THREADS){ int kk=i/BM,mm=i%BM; As[kk][mm]=Ap[(long)(k0+kk)*lda+(m0+mm)]; } }
        for(int i=tid;i<BK*BN;i+=THREADS){
            int kk=i/BN,nn=i%BN;
            float v=Bp[(long)(k0+kk)*Nn+(n0+nn)];
            if (bnS){ int gk=k0+kk; v=fmaxf(fmaf(bnS[gk],v,bnB[gk]),0.f); }
            Bs[kk][nn]=v;
        }
        __syncthreads();
#pragma unroll
        for (int kk=0;kk<BK;kk++){
            float ra[TM],rb[TN];
#pragma unroll
            for(int h=0;h<TM/4;h++) *(float4*)(ra+4*h)=*(const float4*)(&As[kk][ty*TM+4*h]);
#pragma unroll
            for(int h=0;h<TN/4;h++) *(float4*)(rb+4*h)=*(const float4*)(&Bs[kk][tx*TN+4*h]);
#pragma unroll
            for(int i=0;i<TM;i++)
#pragma unroll
                for(int j=0;j<TN;j++) acc[i][j]=fmaf(ra[i],rb[j],acc[i][j]);
        }
        __syncthreads();
    }
#pragma unroll
    for (int i=0;i<TM;i++){
        int m=m0+ty*TM+i; float bv=bias?bias[m]:0.f;
#pragma unroll
        for (int j=0;j<TN;j++){
            int n=n0+tx*TN+j;
            if (SPLITK==1) Cp[(long)m*Nn+n]=acc[i][j]+bv;
            else atomicAdd(&Cp[(long)m*Nn+n],acc[i][j]+((split==0)?bv:0.f));
        }
    }
}

__global__ void bnproj_stats(const float* __restrict__ Y, const float* __restrict__ g,
                             const float* __restrict__ bb, float* __restrict__ aO,
                             float* __restrict__ cO, int Ch){
    int w=blockIdx.x*8+(threadIdx.x>>5), lane=threadIdx.x&31;
    if (w>=Ch) return;
    float s=0.f,s2=0.f;
#pragma unroll
    for(int b=0;b<BATCH;b++){ float v=Y[(((long)b*Ch+w)<<5)+lane]; s+=v; s2=fmaf(v,v,s2); }
#pragma unroll
    for(int o=16;o;o>>=1){ s+=__shfl_xor_sync(~0u,s,o); s2+=__shfl_xor_sync(~0u,s2,o); }
    if (lane==0){
        float inv=1.f/256.f, mean=s*inv, var=s2*inv-mean*mean;
        float a=g[w]*rsqrtf(var+1e-5f); aO[w]=a; cO[w]=bb[w]-a*mean;
    }
}
__global__ void bn2_stats(const float* __restrict__ Z, const float* __restrict__ g,
                          const float* __restrict__ bb, float* __restrict__ aO,
                          float* __restrict__ cO, int Ch){
    int ch=blockIdx.x*256+threadIdx.x; if(ch>=Ch) return;
    float s=0.f;
#pragma unroll
    for(int b=0;b<BATCH;b++) s+=Z[(long)b*Ch+ch];
    float mean=s*0.125f, v=0.f;
#pragma unroll
    for(int b=0;b<BATCH;b++){ float d=Z[(long)b*Ch+ch]-mean; v=fmaf(d,d,v); }
    v*=0.125f;
    float a=g[ch]*rsqrtf(v+1e-5f); aO[ch]=a; cO[ch]=bb[ch]-a*mean;
}
__global__ void softmax_pi(const float* __restrict__ ls, float* __restrict__ sT,
                           float* __restrict__ pi){
    __shared__ float spi[32];
    if (threadIdx.x<32) spi[threadIdx.x]=0.f;
    __syncthreads();
    int idx=blockIdx.x*256+threadIdx.x, pt=idx>>5, lane=idx&31;
    float x=ls[((long)pt<<5)+lane], m=x;
#pragma unroll
    for(int o=16;o;o>>=1) m=fmaxf(m,__shfl_xor_sync(~0u,m,o));
    float e=__expf(x-m), s=e;
#pragma unroll
    for(int o=16;o;o>>=1) s+=__shfl_xor_sync(~0u,s,o);
    float pr=e/s;
    sT[((long)pt<<5)+lane]=pr;
    atomicAdd(&spi[lane],pr);
    __syncthreads();
    if (threadIdx.x<32) atomicAdd(&pi[((blockIdx.x>>9)<<5)+threadIdx.x],spi[threadIdx.x]);
}
__global__ void vlad_fin(float* __restrict__ vlad, const float* __restrict__ pi,
                         float* __restrict__ pool){
    int b=blockIdx.y, d=blockIdx.x*256+threadIdx.x;
    __shared__ float ip[32];
    if (threadIdx.x<32) ip[threadIdx.x]=1.f/fmaxf(pi[(b<<5)+threadIdx.x],1e-4f);
    __syncthreads();
    float4* vp=(float4*)(vlad+(((long)((b<<10)+d))<<5));
    float mx=-CUDART_INF_F;
#pragma unroll
    for(int q=0;q<8;q++){
        float4 v=vp[q];
        v.x*=ip[4*q]; v.y*=ip[4*q+1]; v.z*=ip[4*q+2]; v.w*=ip[4*q+3];
        mx=fmaxf(mx,fmaxf(fmaxf(v.x,v.y),fmaxf(v.z,v.w)));
        vp[q]=v;
    }
    pool[(b<<10)+d]=mx;
}
__global__ void rmu_k(const float* __restrict__ vlad, float* __restrict__ rmu){
    int b=blockIdx.x, k=threadIdx.x>>5, lane=threadIdx.x&31;
    float s=0.f;
    for(int d=lane;d<DIM;d+=32){ float x=vlad[(((long)((b<<10)+d))<<5)+k]; s=fmaf(x,x,s); }
#pragma unroll
    for(int o=16;o;o>>=1) s+=__shfl_xor_sync(~0u,s,o);
    if(lane==0) rmu[(b<<5)+k]=1.f/fmaxf(sqrtf(s),1e-12f);
}
__global__ void cost_fin(float* __restrict__ cost, float* __restrict__ costT,
                         const float* __restrict__ rnacc, const float* __restrict__ rmu){
    int b=blockIdx.y, n=blockIdx.x*256+threadIdx.x;
    __shared__ float rm[32];
    if (threadIdx.x<32) rm[threadIdx.x]=rmu[(b<<5)+threadIdx.x];
    __syncthreads();
    float r2=2.f/fmaxf(sqrtf(rnacc[(b<<12)+n]),1e-12f);
    float4* cp=(float4*)(cost+(((long)((b<<12)+n))<<5));
    float val[32];
#pragma unroll
    for(int q=0;q<8;q++){
        float4 v=cp[q];
        val[4*q]=2.f-v.x*r2*rm[4*q]; val[4*q+1]=2.f-v.y*r2*rm[4*q+1];
        val[4*q+2]=2.f-v.z*r2*rm[4*q+2]; val[4*q+3]=2.f-v.w*r2*rm[4*q+3];
        cp[q]=make_float4(val[4*q],val[4*q+1],val[4*q+2],val[4*q+3]);
    }
#pragma unroll
    for(int k=0;k<32;k++) costT[(((long)((b<<5)+k))<<12)+n]=val[k];
}

__global__ void __launch_bounds__(128)
sinkhorn_fused(const float* __restrict__ cost, const float* __restrict__ costT,
               const float* __restrict__ sT, float* __restrict__ u,
               float* __restrict__ v, float* __restrict__ dsum,
               unsigned* __restrict__ bar, float* __restrict__ out0)
{
    const int tid=threadIdx.x, bid=blockIdx.x;
    const int p = bid*128+tid;
    const int b = p>>12;
    __shared__ float red[128];
    __shared__ float sm[128], ssx[128];
    for (int it=0; it<25; ++it){
        {
            const float* vb = v + (b<<5);
            const float4* cp=(const float4*)(cost+((long)p<<5));
            float t[32];
#pragma unroll
            for(int q=0;q<8;q++){
                float4 c4=cp[q];
                t[4*q]=vb[4*q]-c4.x; t[4*q+1]=vb[4*q+1]-c4.y;
                t[4*q+2]=vb[4*q+2]-c4.z; t[4*q+3]=vb[4*q+3]-c4.w;
            }
            float m=t[0];
#pragma unroll
            for(int k=1;k<32;k++) m=fmaxf(m,t[k]);
            float s=0.f;
#pragma unroll
            for(int k=0;k<32;k++) s+=__expf((t[k]-m)*INV_EPS);
            float un=EPSS*LOGP_C-m-EPSS*__logf(s);
            float dl=fabsf(un-u[p]); u[p]=un;
            red[tid]=dl; __syncthreads();
            for(int st=64;st;st>>=1){ if(tid<st) red[tid]+=red[tid+st]; __syncthreads(); }
            if (tid==0) atomicAdd(&dsum[it],red[0]);
        }
        gbar(bar,bar+1,256u);
        {
            const float* row=costT+((long)bid<<12);
            const float* ub=u+((bid>>5)<<12);
            float mm=-CUDART_INF_F, ss=0.f;
            for(int i=tid;i<NPTS;i+=128){
                float x=ub[i]-row[i];
                if (x>mm){ ss=ss*__expf((mm-x)*INV_EPS)+1.f; mm=x; } else ss+=__expf((x-mm)*INV_EPS);
            }
            sm[tid]=mm; ssx[tid]=ss; __syncthreads();
            for(int st=64;st;st>>=1){
                if(tid<st){
                    float m1=sm[tid],s1=ssx[tid],m2=sm[tid+st],s2=ssx[tid+st];
                    float M=fmaxf(m1,m2);
                    ssx[tid]=s1*__expf((m1-M)*INV_EPS)+s2*__expf((m2-M)*INV_EPS);
                    sm[tid]=M;
                }
                __syncthreads();
            }
            if (tid==0){
                float vn=EPSS*LOGQ_C-sm[0]-EPSS*__logf(ssx[0]);
                atomicAdd(&dsum[it],fabsf(vn-v[bid]));
                v[bid]=vn;
            }
        }
        gbar(bar,bar+1,256u);
        float dd = *((volatile float*)&dsum[it]);
        if (dd*0.125f < 1e-3f) break;
    }
    {
        const float* vb = v + (b<<5);
        float uu = u[p];
        const float4* cp=(const float4*)(cost+((long)p<<5));
        const float4* sp=(const float4*)(sT+((long)p<<5));
        float acc=0.f;
#pragma unroll
        for(int q=0;q<8;q++){
            float4 c4=cp[q]; float4 s4=sp[q];
            acc+=__expf((uu+vb[4*q]-c4.x)*INV_EPS)*__logf(fmaxf(s4.x,1e-38f));
            acc+=__expf((uu+vb[4*q+1]-c4.y)*INV_EPS)*__logf(fmaxf(s4.y,1e-38f));
            acc+=__expf((uu+vb[4*q+2]-c4.z)*INV_EPS)*__logf(fmaxf(s4.z,1e-38f));
            acc+=__expf((uu+vb[4*q+3]-c4.w)*INV_EPS)*__logf(fmaxf(s4.w,1e-38f));
        }
        red[tid]=acc; __syncthreads();
        for(int st=64;st;st>>=1){ if(tid<st) red[tid]+=red[tid+st]; __syncthreads(); }
        if (tid==0) atomicAdd(out0,red[0]*(-0.125f));
    }
}

template<bool ACT>
__global__ void fc_k(const float* __restrict__ X, const float* __restrict__ W,
                     float* __restrict__ C, int O, int Kin, const float* __restrict__ bias,
                     const float* __restrict__ a, const float* __restrict__ c){
    int gw=(blockIdx.x*256+threadIdx.x)>>5, lane=threadIdx.x&31;
    int b=gw/O, o=gw-b*O;
    const float* x=X+(long)b*Kin;
    const float* wr=W+(long)o*Kin;
    float s=0.f;
    for(int k=lane;k<Kin;k+=32){
        float xv=x[k];
        if (ACT) xv=fmaxf(fmaf(a[k],xv,c[k]),0.f);
        s=fmaf(xv,wr[k],s);
    }
#pragma unroll
    for(int o2=16;o2;o2>>=1) s+=__shfl_xor_sync(~0u,s,o2);
    if(lane==0) C[(long)b*O+o]=s+(bias?bias[o]:0.f);
}

extern "C" void kernel_launch(void* const* d_in, const int* in_sizes, int n_in,
                              void* d_out, int out_size)
{
    const float *F=(const float*)d_in[0];
    const float *cw1=(const float*)d_in[1], *cg1=(const float*)d_in[3], *ct1=(const float*)d_in[4];
    const float *cw2=(const float*)d_in[5], *cg2=(const float*)d_in[7], *ct2=(const float*)d_in[8];
    const float *cw3=(const float*)d_in[9], *cb3=(const float*)d_in[10];
    const float *pw1=(const float*)d_in[11], *pg1=(const float*)d_in[13], *pt1=(const float*)d_in[14];
    const float *pw2=(const float*)d_in[15], *pg2=(const float*)d_in[17], *pt2=(const float*)d_in[18];
    const float *pw3=(const float*)d_in[19], *pb3=(const float*)d_in[20];
    const float *mw1=(const float*)d_in[21], *mg1=(const float*)d_in[23], *mt1=(const float*)d_in[24];
    const float *mw2=(const float*)d_in[25], *mg2=(const float*)d_in[27], *mt2=(const float*)d_in[28];
    const float *mw3=(const float*)d_in[29], *mb3=(const float*)d_in[30];
    float* out=(float*)d_out;

    static float* S=nullptr; static int* FL=nullptr;
    static __nv_bfloat16 *FTh,*FTl,*Fh,*Fl,*Wh,*Wl,*SCh,*SCl,*VTh,*VTl;
    static float *YT,*YT2;
    static cudaStream_t s2;
    static cudaEvent_t ev1, ev2;
    if (!S){
        cudaGetSymbolAddress((void**)&S,d_scratch);
        cudaGetSymbolAddress((void**)&FL,d_flags);
        cudaGetSymbolAddress((void**)&FTh,d_FTh); cudaGetSymbolAddress((void**)&FTl,d_FTl);
        cudaGetSymbolAddress((void**)&Fh,d_Fh);   cudaGetSymbolAddress((void**)&Fl,d_Fl);
        cudaGetSymbolAddress((void**)&Wh,d_Wh);   cudaGetSymbolAddress((void**)&Wl,d_Wl);
        cudaGetSymbolAddress((void**)&SCh,d_SCh); cudaGetSymbolAddress((void**)&SCl,d_SCl);
        cudaGetSymbolAddress((void**)&VTh,d_VTh); cudaGetSymbolAddress((void**)&VTl,d_VTl);
        cudaGetSymbolAddress((void**)&YT,d_YT);   cudaGetSymbolAddress((void**)&YT2,d_YT2);
        cudaStreamCreateWithFlags(&s2, cudaStreamNonBlocking);
        cudaEventCreateWithFlags(&ev1, cudaEventDisableTiming);
        cudaEventCreateWithFlags(&ev2, cudaEventDisableTiming);
        cudaFuncSetAttribute(hmma_gemm<1024,128,2,4,512,false,false>,cudaFuncAttributeMaxDynamicSharedMemorySize,81920);
        cudaFuncSetAttribute(hmma_gemm<512,128,2,4,512,false,true>,cudaFuncAttributeMaxDynamicSharedMemorySize,81920);
        cudaFuncSetAttribute(hmma_gemm<512,32,8,1,32,true,true>,cudaFuncAttributeMaxDynamicSharedMemorySize,51200);
        cudaFuncSetAttribute(hmma_gemm<4096,32,8,1,32,false,false>,cudaFuncAttributeMaxDynamicSharedMemorySize,51200);
        cudaFuncSetAttribute(hmma_gemm<1024,32,8,1,32,false,false>,cudaFuncAttributeMaxDynamicSharedMemorySize,51200);
    }
    float *LS=S+OFF_LS,*ST=S+OFF_ST,*COST=S+OFF_COST,*COSTT=S+OFF_COSTT;
    float *RN=S+OFF_RN,*POOL=S+OFF_POOL,*P1=S+OFF_P1,*P2=S+OFF_P2;
    float *Z1=S+OFF_Z1,*Z2=S+OFF_Z2,*BNC=S+OFF_BN;
    float *VLAD=S+OFF_VLAD,*PI=S+OFF_PI,*U=S+OFF_U,*V=S+OFF_V,*RMU=S+OFF_RMU;
    float *ACC=S+OFF_ACC,*DS=S+OFF_DSUM;
    float *a1=BNC,*c1=BNC+512,*a2=BNC+1024,*c2=BNC+1536;
    float *ap1=BNC+2048,*cp1=BNC+2560,*ap2=BNC+3072,*cp2=BNC+3584;
    float *am1=BNC+4096,*cm1=BNC+4608,*am2=BNC+5120,*cm2=BNC+5632;

    init_k<<<1,32>>>(FL);
    zero_k<<<(int)((ZTAIL+255)/256),256>>>(S+OFF_VLAD,ZTAIL);
    zero_k<<<129,256>>>(out,32897);
    w_split<<<3137,256>>>(cw1,cw2,cw3,Wh,Wl);
    ft_split<<<dim3(128,32,8),dim3(32,8)>>>(F,FTh,FTl,Fh,Fl,RN);

    // score head on HMMA (bf16x3); BN-relu+split fused into A-load of G2/G3
    hmma_gemm<1024,128,2,4,512,false,false><<<dim3(4,32,8),256,81920>>>(
        FTh,FTl,4194304L, nullptr,nullptr,nullptr, Wh,Wl,0L, YT,2097152L,nullptr);
    bnT_partial<<<128,512>>>(YT,ACC);
    bnT_final<<<1,512>>>(ACC,cg1,ct1,a1,c1);
    hmma_gemm<512,128,2,4,512,false,true><<<dim3(4,32,8),256,81920>>>(
        nullptr,nullptr,2097152L, YT,a1,c1, Wh+524288,Wl+524288,0L, YT2,2097152L,nullptr);
    bnT_partial<<<128,512>>>(YT2,ACC);
    bnT_final<<<1,512>>>(ACC,cg2,ct2,a2,c2);
    hmma_gemm<512,32,8,1,32,true,true><<<dim3(1,32,8),256,51200>>>(
        nullptr,nullptr,2097152L, YT2,a2,c2, Wh+786432,Wl+786432,0L, LS,131072L,cb3);

    softmax_pi<<<4096,256>>>(LS,ST,PI);
    tr_split<<<dim3(128,1,8),dim3(32,8)>>>(ST,SCh,SCl,4096);
    hmma_gemm<4096,32,8,1,32,false,false><<<dim3(1,8,8),256,51200>>>(
        Fh,Fl,4194304L, nullptr,nullptr,nullptr, SCh,SCl,131072L, VLAD,32768L,nullptr);
    vlad_fin<<<dim3(4,8),256>>>(VLAD,PI,POOL);
    rmu_k<<<8,1024>>>(VLAD,RMU);

    // ---- fork: projector conv + predictor MLP (depend only on VLAD/POOL) run on s2,
    //      overlapping the cost GEMM + Sinkhorn chain on the main stream ----
    cudaEventRecord(ev1, 0);
    cudaStreamWaitEvent(s2, ev1, 0);
    gemm_k<128,32,16,8,4,false,8><<<dim3(1,4,64),128,0,s2>>>(
        pw1,0,DIM, VLAD,(long)DIM*KCL, P1,(long)HID*KCL, HID,KCL,DIM, nullptr,nullptr,nullptr);
    bnproj_stats<<<64,256,0,s2>>>(P1,pg1,pt1,ap1,cp1,HID);
    gemm_k<128,32,16,8,4,false,8><<<dim3(1,4,64),128,0,s2>>>(
        pw2,0,HID, P1,(long)HID*KCL, P2,(long)HID*KCL, HID,KCL,HID, nullptr,ap1,cp1);
    bnproj_stats<<<64,256,0,s2>>>(P2,pg2,pt2,ap2,cp2,HID);
    gemm_k<64,32,16,4,4,false,8><<<dim3(1,2,64),128,0,s2>>>(
        pw3,0,HID, P2,(long)HID*KCL, out+1,(long)PRJ*KCL, PRJ,KCL,HID, pb3,ap2,cp2);
    fc_k<false><<<512,256,0,s2>>>(POOL,mw1,Z1,HID,DIM,nullptr,nullptr,nullptr);
    bn2_stats<<<2,256,0,s2>>>(Z1,mg1,mt1,am1,cm1,HID);
    fc_k<true ><<<512,256,0,s2>>>(Z1,mw2,Z2,HID,HID,nullptr,am1,cm1);
    bn2_stats<<<2,256,0,s2>>>(Z2,mg2,mt2,am2,cm2,HID);
    fc_k<true ><<<128,256,0,s2>>>(Z2,mw3,out+1+32768,PRJ,HID,mb3,am2,cm2);
    cudaEventRecord(ev2, s2);

    // main stream: cost + Sinkhorn + loss
    tr_split<<<dim3(32,1,8),dim3(32,8)>>>(VLAD,VTh,VTl,1024);
    hmma_gemm<1024,32,8,1,32,false,false><<<dim3(1,32,8),256,51200>>>(
        FTh,FTl,4194304L, nullptr,nullptr,nullptr, VTh,VTl,32768L, COST,131072L,nullptr);
    cost_fin<<<dim3(16,8),256>>>(COST,COSTT,RN,RMU);
    sinkhorn_fused<<<256,128>>>(COST,COSTT,ST,U,V,DS,(unsigned*)(FL+2),out);

    // join
    cudaStreamWaitEvent(0, ev2, 0);
}

// round 17
// speedup vs baseline: 1.1645x; 1.1189x over previous
#include <cuda_runtime.h>
#include <cuda_bf16.h>
#include <math_constants.h>
#include <stdint.h>

#define BATCH 8
#define DIM 1024
#define NPTS 4096
#define KCL 32
#define HID 512
#define PRJ 128
#define EPSS 1e-3f
#define INV_EPS 1000.0f
#define LOGP_C (-8.3177252f)
#define LOGQ_C (-3.4657356f)

constexpr long OFF_LS=0, OFF_ST=1048576, OFF_COST=2097152, OFF_COSTT=3145728;
constexpr long OFF_POOL=4194304, OFF_Z1=4202496, OFF_Z2=4206592, OFF_BN=4210688;
constexpr long OFF_VLAD=4216832, OFF_PI=4478976, OFF_U=4479232, OFF_V=4512000;
constexpr long OFF_RMU=4512256, OFF_ACC=4512512, OFF_DSUM=4513536, OFF_RN=4513568;
constexpr long OFF_P1=4546336, OFF_P2=4677408;
constexpr long SCRATCH_SZ=4808480;
constexpr long ZTAIL=SCRATCH_SZ-OFF_VLAD;

static __device__ float d_scratch[SCRATCH_SZ];
static __device__ int   d_flags[4];
static __device__ __nv_bfloat16 d_FTh[33554432], d_FTl[33554432];
static __device__ __nv_bfloat16 d_Fh[33554432],  d_Fl[33554432];
static __device__ __nv_bfloat16 d_Wh[802816],    d_Wl[802816];
static __device__ __nv_bfloat16 d_SCh[1048576],  d_SCl[1048576];
static __device__ __nv_bfloat16 d_VTh[262144],   d_VTl[262144];
static __device__ float d_YT[16777216];
static __device__ float d_YT2[16777216];

__device__ __forceinline__ uint32_t smem_u32(const void* p){
    uint32_t a; asm("{ .reg .u64 t; cvta.to.shared.u64 t,%1; cvt.u32.u64 %0,t; }":"=r"(a):"l"(p)); return a;
}
#define CP16(dst,src) asm volatile("cp.async.cg.shared.global [%0],[%1],16;"::"r"(dst),"l"(src):"memory")
#define CPCOMMIT() asm volatile("cp.async.commit_group;":::"memory")
#define CPWAIT1() asm volatile("cp.async.wait_group 1;":::"memory")
#define CPWAIT0() asm volatile("cp.async.wait_group 0;":::"memory")
#define LDM4(r0,r1,r2,r3,ad) asm volatile("ldmatrix.sync.aligned.m8n8.x4.shared.b16 {%0,%1,%2,%3},[%4];":"=r"(r0),"=r"(r1),"=r"(r2),"=r"(r3):"r"(ad))
#define STS64v(a,r0,r1) asm volatile("st.shared.v2.b32 [%0],{%1,%2};"::"r"(a),"r"(r0),"r"(r1):"memory")
#define MMA(d,a,b) asm volatile("mma.sync.aligned.m16n8k16.row.col.f32.bf16.bf16.f32 {%0,%1,%2,%3},{%4,%5,%6,%7},{%8,%9},{%0,%1,%2,%3};" \
  :"+f"((d)[0]),"+f"((d)[1]),"+f"((d)[2]),"+f"((d)[3]) \
  :"r"((a)[0]),"r"((a)[1]),"r"((a)[2]),"r"((a)[3]),"r"((b)[0]),"r"((b)[1]))

__device__ __forceinline__ void gbar(unsigned* cnt, unsigned* gen, unsigned nb){
    __syncthreads();
    if (threadIdx.x==0){
        unsigned g = *((volatile unsigned*)gen);
        __threadfence();
        if (atomicAdd(cnt,1u)==nb-1u){ *cnt=0u; __threadfence(); atomicAdd(gen,1u); }
        else { while (*((volatile unsigned*)gen)==g) {} }
    }
    __syncthreads();
}
__device__ __forceinline__ uint32_t pk(float v0, float v1){
    __nv_bfloat162 h(__float2bfloat16(v0),__float2bfloat16(v1));
    return *(uint32_t*)&h;
}

// Y[row,ch] = sum_k A[row,k]*B[ch,k], bf16x3 split, fp32 acc.
// BNA: A is fp32 Af with relu(bna*x+bnc) + h/l split in the load path.
// SPLITK>1: blockIdx.z = batch*SPLITK+split, ATOMIC epilogue (target pre-zeroed).
template<int KTOT,int BN,int WM,int WN,int CHTOT,bool BIAS,bool BNA,int SPLITK=1,bool ATOMIC=false>
__global__ void __launch_bounds__(256,1)
hmma_gemm(const __nv_bfloat16* __restrict__ Ah, const __nv_bfloat16* __restrict__ Al, long sAb,
          const float* __restrict__ Af, const float* __restrict__ bna, const float* __restrict__ bnc,
          const __nv_bfloat16* __restrict__ Bh, const __nv_bfloat16* __restrict__ Bl, long sBb,
          float* __restrict__ Y, long sYb, const float* __restrict__ bias)
{
    constexpr int MI = 128/(WM*16), NI = BN/(WN*8);
    constexpr int KT = KTOT/32;
    constexpr int KTL = KT/SPLITK;          // K-tiles this block processes
    constexpr int SS = 20480 + BN*160;
    extern __shared__ __align__(16) char smem[];
    const uint32_t sm0 = smem_u32(smem);
    const int tid=threadIdx.x, lane=tid&31, w=tid>>5;
    const int wm = w % WM, wn = w / WM;
    const int b=blockIdx.z/SPLITK, split=blockIdx.z%SPLITK;
    const int pt0=blockIdx.y*128, ch0=blockIdx.x*BN;
    const int tOff = split*KTL;

    const __nv_bfloat16* pAh = BNA ? nullptr : Ah + b*sAb + (long)pt0*KTOT;
    const __nv_bfloat16* pAl = BNA ? nullptr : Al + b*sAb + (long)pt0*KTOT;
    const float*         pAf = BNA ? Af + b*sAb + (long)pt0*KTOT : nullptr;
    const __nv_bfloat16* pBh = Bh + b*sBb + (long)ch0*KTOT;
    const __nv_bfloat16* pBl = Bl + b*sBb + (long)ch0*KTOT;
    float* Yb = Y + b*sYb;

    float acc[MI][NI][4];
#pragma unroll
    for(int i=0;i<MI;i++)
#pragma unroll
        for(int j=0;j<NI;j++){ acc[i][j][0]=0.f;acc[i][j][1]=0.f;acc[i][j][2]=0.f;acc[i][j][3]=0.f; }

    float4 av[4];
    auto loadA_regs = [&](int t){
        const int k0 = (tOff+t)*32;
#pragma unroll
        for (int i=0;i<4;i++){
            int idx = tid + i*256; int r = idx>>3, c = idx&7;
            av[i] = *(const float4*)(pAf + (long)r*KTOT + k0 + c*4);
        }
    };
    auto stsA = [&](int t){
        const uint32_t st = sm0 + (t&1)*SS;
        const int k0 = (tOff+t)*32;
#pragma unroll
        for (int i=0;i<4;i++){
            int idx = tid + i*256; int r = idx>>3, c = idx&7;
            int ch = k0 + c*4;
            float v0=fmaxf(fmaf(__ldg(bna+ch),  av[i].x,__ldg(bnc+ch)),  0.f);
            float v1=fmaxf(fmaf(__ldg(bna+ch+1),av[i].y,__ldg(bnc+ch+1)),0.f);
            float v2=fmaxf(fmaf(__ldg(bna+ch+2),av[i].z,__ldg(bnc+ch+2)),0.f);
            float v3=fmaxf(fmaf(__ldg(bna+ch+3),av[i].w,__ldg(bnc+ch+3)),0.f);
            __nv_bfloat16 h0=__float2bfloat16(v0),h1=__float2bfloat16(v1);
            __nv_bfloat16 h2=__float2bfloat16(v2),h3=__float2bfloat16(v3);
            uint32_t H0=pk(v0,v1), H1=pk(v2,v3);
            uint32_t L0=pk(v0-__bfloat162float(h0), v1-__bfloat162float(h1));
            uint32_t L1=pk(v2-__bfloat162float(h2), v3-__bfloat162float(h3));
            uint32_t ad = st + r*80 + c*8;
            STS64v(ad, H0, H1);
            STS64v(ad+10240, L0, L1);
        }
    };
    auto load_stage = [&](int t){
        const int k0 = (tOff+t)*32;
        const uint32_t st = sm0 + (t&1)*SS;
        if (!BNA){
#pragma unroll
            for (int i=0;i<2;i++){
                int idx = tid + i*256; int r = idx>>2, c = idx&3;
                CP16(st + r*80 + c*16,         pAh + (long)r*KTOT + k0 + c*8);
                CP16(st + 10240 + r*80 + c*16, pAl + (long)r*KTOT + k0 + c*8);
            }
        }
#pragma unroll
        for (int i=0;i<(BN*4+255)/256;i++){
            int idx = tid + i*256;
            if ((BN*4)%256==0 || idx<BN*4){
                int r = idx>>2, c = idx&3;
                CP16(st + 20480 + r*80 + c*16,         pBh + (long)r*KTOT + k0 + c*8);
                CP16(st + 20480 + BN*80 + r*80 + c*16, pBl + (long)r*KTOT + k0 + c*8);
            }
        }
        CPCOMMIT();
    };

    if (BNA) loadA_regs(0);
    load_stage(0);
    if (KTL>1) load_stage(1);

    for (int t=0;t<KTL;t++){
        if (BNA) stsA(t);
        if (t==KTL-1) { CPWAIT0(); } else { CPWAIT1(); }
        __syncthreads();
        if (BNA && t+1<KTL) loadA_regs(t+1);
        const uint32_t st = sm0 + (t&1)*SS;
#pragma unroll
        for (int ks=0;ks<2;ks++){
            const int kk=ks*16;
            uint32_t ah[MI][4], al[MI][4], bh[NI][2], bl[NI][2];
            const uint32_t koff = (kk + ((lane>>4)<<3))*2;
            uint32_t abase = st + (wm*MI*16 + (lane&15))*80 + koff;
#pragma unroll
            for (int mi=0;mi<MI;mi++){
                LDM4(ah[mi][0],ah[mi][1],ah[mi][2],ah[mi][3], abase + mi*16*80);
                LDM4(al[mi][0],al[mi][1],al[mi][2],al[mi][3], abase + mi*16*80 + 10240);
            }
            uint32_t bbase = st + 20480 + (wn*NI*8 + (lane&15))*80 + koff;
#pragma unroll
            for (int nj=0;nj<NI/2;nj++){
                uint32_t r0,r1,r2,r3;
                LDM4(r0,r1,r2,r3, bbase + nj*16*80);
                bh[2*nj][0]=r0; bh[2*nj][1]=r2; bh[2*nj+1][0]=r1; bh[2*nj+1][1]=r3;
                LDM4(r0,r1,r2,r3, bbase + nj*16*80 + BN*80);
                bl[2*nj][0]=r0; bl[2*nj][1]=r2; bl[2*nj+1][0]=r1; bl[2*nj+1][1]=r3;
            }
#pragma unroll
            for (int mi=0;mi<MI;mi++)
#pragma unroll
                for (int ni=0;ni<NI;ni++){
                    MMA(acc[mi][ni], ah[mi], bh[ni]);
                    MMA(acc[mi][ni], ah[mi], bl[ni]);
                    MMA(acc[mi][ni], al[mi], bh[ni]);
                }
        }
        __syncthreads();
        if (t+2 < KTL) load_stage(t+2);
    }

    const int rbase = pt0 + wm*MI*16 + (lane>>2);
    const int cbase = ch0 + wn*NI*8 + (lane&3)*2;
#pragma unroll
    for (int mi=0;mi<MI;mi++)
#pragma unroll
        for (int ni=0;ni<NI;ni++){
            int r = rbase + mi*16, c = cbase + ni*8;
            float bv0 = BIAS ? bias[c] : 0.f, bv1 = BIAS ? bias[c+1] : 0.f;
            float* y0 = Yb + (long)r*CHTOT + c;
            float* y1 = y0 + 8*CHTOT;
            if (ATOMIC){
                atomicAdd(y0,   acc[mi][ni][0]+bv0); atomicAdd(y0+1, acc[mi][ni][1]+bv1);
                atomicAdd(y1,   acc[mi][ni][2]+bv0); atomicAdd(y1+1, acc[mi][ni][3]+bv1);
            } else {
                y0[0]=acc[mi][ni][0]+bv0; y0[1]=acc[mi][ni][1]+bv1;
                y1[0]=acc[mi][ni][2]+bv0; y1[1]=acc[mi][ni][3]+bv1;
            }
        }
}

__global__ void w_split(const float* __restrict__ w1, const float* __restrict__ w2,
                        const float* __restrict__ w3, __nv_bfloat16* __restrict__ H,
                        __nv_bfloat16* __restrict__ L){
    int i=blockIdx.x*256+threadIdx.x; if(i>=802816) return;
    float v = (i<524288)? w1[i] : (i<786432? w2[i-524288] : w3[i-786432]);
    __nv_bfloat16 h=__float2bfloat16(v); H[i]=h; L[i]=__float2bfloat16(v-__bfloat162float(h));
}
__global__ void ft_split(const float* __restrict__ F, __nv_bfloat16* __restrict__ TH,
                         __nv_bfloat16* __restrict__ TL, __nv_bfloat16* __restrict__ DH,
                         __nv_bfloat16* __restrict__ DL, float* __restrict__ rn){
    __shared__ float t[32][33];
    __shared__ float part[8][32];
    int b=blockIdx.z, n0=blockIdx.x*32, d0=blockIdx.y*32, tx=threadIdx.x, ty=threadIdx.y;
    const float* Fb=F+((long)b<<22);
#pragma unroll
    for (int j=0;j<4;j++){
        float v=Fb[(long)(d0+ty*4+j)*4096+n0+tx];
        t[ty*4+j][tx]=v;
        long od=((long)(b*1024)+d0+ty*4+j)*4096+n0+tx;
        __nv_bfloat16 h=__float2bfloat16(v); DH[od]=h; DL[od]=__float2bfloat16(v-__bfloat162float(h));
    }
    __syncthreads();
    float s=0.f;
#pragma unroll
    for (int j=0;j<4;j++){
        float v=t[tx][ty*4+j];
        long o=((long)(b*4096)+n0+ty*4+j)*1024+d0+tx;
        __nv_bfloat16 h=__float2bfloat16(v); TH[o]=h; TL[o]=__float2bfloat16(v-__bfloat162float(h));
        float w2=t[ty*4+j][tx]; s=fmaf(w2,w2,s);
    }
    part[ty][tx]=s; __syncthreads();
    if (ty==0){
        float tot=0.f;
#pragma unroll
        for(int k=0;k<8;k++) tot+=part[k][tx];
        atomicAdd(&rn[(b<<12)+n0+tx], tot);
    }
}
__global__ void tr_split(const float* __restrict__ X, __nv_bfloat16* __restrict__ H,
                         __nv_bfloat16* __restrict__ L, int R){
    __shared__ float t[32][33];
    int b=blockIdx.z, r0=blockIdx.x*32, tx=threadIdx.x, ty=threadIdx.y;
#pragma unroll
    for (int j=0;j<4;j++)
        t[ty*4+j][tx]=X[((long)b*R+r0+ty*4+j)*32+tx];
    __syncthreads();
#pragma unroll
    for (int j=0;j<4;j++){
        float v=t[tx][ty*4+j];
        long o=((long)(b*32)+ty*4+j)*R + r0+tx;
        __nv_bfloat16 h=__float2bfloat16(v); H[o]=h; L[o]=__float2bfloat16(v-__bfloat162float(h));
    }
}
__global__ void bnT_partial(const float* __restrict__ Y, float* __restrict__ acc){
    int ch=threadIdx.x; long r0=(long)blockIdx.x*256;
    const float* p=Y+r0*512+ch;
    float s=0.f,s2=0.f;
    for (int r=0;r<256;r++){ float v=p[(long)r*512]; s+=v; s2=fmaf(v,v,s2); }
    atomicAdd(&acc[ch],s); atomicAdd(&acc[512+ch],s2);
}
__global__ void bnT_final(float* __restrict__ acc, const float* __restrict__ g,
                          const float* __restrict__ bb, float* __restrict__ aO, float* __restrict__ cO){
    int ch=threadIdx.x;
    float inv=1.f/32768.f, mean=acc[ch]*inv, var=acc[512+ch]*inv-mean*mean;
    float a=g[ch]*rsqrtf(var+1e-5f);
    aO[ch]=a; cO[ch]=bb[ch]-a*mean; acc[ch]=0.f; acc[512+ch]=0.f;
}
__global__ void zero_k(float* __restrict__ p, long n){
    long i=(long)blockIdx.x*256+threadIdx.x; if(i<n) p[i]=0.f;
}
__global__ void init_k(int* f){ if(threadIdx.x<4) f[threadIdx.x]=0; }

template<int BM,int BN,int BK,int TM,int TN,bool TA,int SPLITK>
__global__ void __launch_bounds__((BM/TM)*(BN/TN))
gemm_k(const float* __restrict__ A, long strideA, int lda,
       const float* __restrict__ B, long strideB,
       float* __restrict__ C, long strideC, int M, int Nn, int Kk,
       const float* __restrict__ bias, const float* __restrict__ bnS, const float* __restrict__ bnB)
{
    constexpr int THREADS=(BM/TM)*(BN/TN);
    const int bz=blockIdx.z, batch=bz/SPLITK, split=bz%SPLITK;
    const int kPer=Kk/SPLITK, kBeg=split*kPer, kEnd=kBeg+kPer;
    const float* Ap=A+(long)batch*strideA;
    const float* Bp=B+(long)batch*strideB;
    float* Cp=C+(long)batch*strideC;
    __shared__ __align__(16) float As[BK][BM+4];
    __shared__ __align__(16) float Bs[BK][BN+4];
    const int tid=threadIdx.x, tx=tid%(BN/TN), ty=tid/(BN/TN);
    const int m0=blockIdx.y*BM, n0=blockIdx.x*BN;
    float acc[TM][TN];
#pragma unroll
    for(int i=0;i<TM;i++)
#pragma unroll
        for(int j=0;j<TN;j++) acc[i][j]=0.f;
    for (int k0=kBeg;k0<kEnd;k0+=BK){
        if (!TA){ for(int i=tid;i<BM*BK;i+=THREADS){ int mm=i/BK,kk=i%BK; As[kk][mm]=Ap[(long)(m0+mm)*lda+(k0+kk)]; } }
        else    { for(int i=tid;i<BM*BK;i+=THREADS){ int kk=i/BM,mm=i%BM; As[kk][mm]=Ap[(long)(k0+kk)*lda+(m0+mm)]; } }
        for(int i=tid;i<BK*BN;i+=THREADS){
            int kk=i/BN,nn=i%BN;
            float v=Bp[(long)(k0+kk)*Nn+(n0+nn)];
            if (bnS){ int gk=k0+kk; v=fmaxf(fmaf(bnS[gk],v,bnB[gk]),0.f); }
            Bs[kk][nn]=v;
        }
        __syncthreads();
#pragma unroll
        for (int kk=0;kk<BK;kk++){
            float ra[TM],rb[TN];
#pragma unroll
            for(int h=0;h<TM/4;h++) *(float4*)(ra+4*h)=*(const float4*)(&As[kk][ty*TM+4*h]);
#pragma unroll
            for(int h=0;h<TN/4;h++) *(float4*)(rb+4*h)=*(const float4*)(&Bs[kk][tx*TN+4*h]);
#pragma unroll
            for(int i=0;i<TM;i++)
#pragma unroll
                for(int j=0;j<TN;j++) acc[i][j]=fmaf(ra[i],rb[j],acc[i][j]);
        }
        __syncthreads();
    }
#pragma unroll
    for (int i=0;i<TM;i++){
        int m=m0+ty*TM+i; float bv=bias?bias[m]:0.f;
#pragma unroll
        for (int j=0;j<TN;j++){
            int n=n0+tx*TN+j;
            if (SPLITK==1) Cp[(long)m*Nn+n]=acc[i][j]+bv;
            else atomicAdd(&Cp[(long)m*Nn+n],acc[i][j]+((split==0)?bv:0.f));
        }
    }
}

__global__ void bnproj_stats(const float* __restrict__ Y, const float* __restrict__ g,
                             const float* __restrict__ bb, float* __restrict__ aO,
                             float* __restrict__ cO, int Ch){
    int w=blockIdx.x*8+(threadIdx.x>>5), lane=threadIdx.x&31;
    if (w>=Ch) return;
    float s=0.f,s2=0.f;
#pragma unroll
    for(int b=0;b<BATCH;b++){ float v=Y[(((long)b*Ch+w)<<5)+lane]; s+=v; s2=fmaf(v,v,s2); }
#pragma unroll
    for(int o=16;o;o>>=1){ s+=__shfl_xor_sync(~0u,s,o); s2+=__shfl_xor_sync(~0u,s2,o); }
    if (lane==0){
        float inv=1.f/256.f, mean=s*inv, var=s2*inv-mean*mean;
        float a=g[w]*rsqrtf(var+1e-5f); aO[w]=a; cO[w]=bb[w]-a*mean;
    }
}
__global__ void bn2_stats(const float* __restrict__ Z, const float* __restrict__ g,
                          const float* __restrict__ bb, float* __restrict__ aO,
                          float* __restrict__ cO, int Ch){
    int ch=blockIdx.x*256+threadIdx.x; if(ch>=Ch) return;
    float s=0.f;
#pragma unroll
    for(int b=0;b<BATCH;b++) s+=Z[(long)b*Ch+ch];
    float mean=s*0.125f, v=0.f;
#pragma unroll
    for(int b=0;b<BATCH;b++){ float d=Z[(long)b*Ch+ch]-mean; v=fmaf(d,d,v); }
    v*=0.125f;
    float a=g[ch]*rsqrtf(v+1e-5f); aO[ch]=a; cO[ch]=bb[ch]-a*mean;
}
__global__ void softmax_pi(const float* __restrict__ ls, float* __restrict__ sT,
                           float* __restrict__ pi){
    __shared__ float spi[32];
    if (threadIdx.x<32) spi[threadIdx.x]=0.f;
    __syncthreads();
    int idx=blockIdx.x*256+threadIdx.x, pt=idx>>5, lane=idx&31;
    float x=ls[((long)pt<<5)+lane], m=x;
#pragma unroll
    for(int o=16;o;o>>=1) m=fmaxf(m,__shfl_xor_sync(~0u,m,o));
    float e=__expf(x-m), s=e;
#pragma unroll
    for(int o=16;o;o>>=1) s+=__shfl_xor_sync(~0u,s,o);
    float pr=e/s;
    sT[((long)pt<<5)+lane]=pr;
    atomicAdd(&spi[lane],pr);
    __syncthreads();
    if (threadIdx.x<32) atomicAdd(&pi[((blockIdx.x>>9)<<5)+threadIdx.x],spi[threadIdx.x]);
}
__global__ void vlad_fin(float* __restrict__ vlad, const float* __restrict__ pi,
                         float* __restrict__ pool){
    int b=blockIdx.y, d=blockIdx.x*256+threadIdx.x;
    __shared__ float ip[32];
    if (threadIdx.x<32) ip[threadIdx.x]=1.f/fmaxf(pi[(b<<5)+threadIdx.x],1e-4f);
    __syncthreads();
    float4* vp=(float4*)(vlad+(((long)((b<<10)+d))<<5));
    float mx=-CUDART_INF_F;
#pragma unroll
    for(int q=0;q<8;q++){
        float4 v=vp[q];
        v.x*=ip[4*q]; v.y*=ip[4*q+1]; v.z*=ip[4*q+2]; v.w*=ip[4*q+3];
        mx=fmaxf(mx,fmaxf(fmaxf(v.x,v.y),fmaxf(v.z,v.w)));
        vp[q]=v;
    }
    pool[(b<<10)+d]=mx;
}
__global__ void rmu_k(const float* __restrict__ vlad, float* __restrict__ rmu){
    int b=blockIdx.x, k=threadIdx.x>>5, lane=threadIdx.x&31;
    float s=0.f;
    for(int d=lane;d<DIM;d+=32){ float x=vlad[(((long)((b<<10)+d))<<5)+k]; s=fmaf(x,x,s); }
#pragma unroll
    for(int o=16;o;o>>=1) s+=__shfl_xor_sync(~0u,s,o);
    if(lane==0) rmu[(b<<5)+k]=1.f/fmaxf(sqrtf(s),1e-12f);
}
__global__ void cost_fin(float* __restrict__ cost, float* __restrict__ costT,
                         const float* __restrict__ rnacc, const float* __restrict__ rmu){
    int b=blockIdx.y, n=blockIdx.x*256+threadIdx.x;
    __shared__ float rm[32];
    if (threadIdx.x<32) rm[threadIdx.x]=rmu[(b<<5)+threadIdx.x];
    __syncthreads();
    float r2=2.f/fmaxf(sqrtf(rnacc[(b<<12)+n]),1e-12f);
    float4* cp=(float4*)(cost+(((long)((b<<12)+n))<<5));
    float val[32];
#pragma unroll
    for(int q=0;q<8;q++){
        float4 v=cp[q];
        val[4*q]=2.f-v.x*r2*rm[4*q]; val[4*q+1]=2.f-v.y*r2*rm[4*q+1];
        val[4*q+2]=2.f-v.z*r2*rm[4*q+2]; val[4*q+3]=2.f-v.w*r2*rm[4*q+3];
        cp[q]=make_float4(val[4*q],val[4*q+1],val[4*q+2],val[4*q+3]);
    }
#pragma unroll
    for(int k=0;k<32;k++) costT[(((long)((b<<5)+k))<<12)+n]=val[k];
}

// Sinkhorn + loss, persistent, 128 blocks x 256 threads (1 u-point per thread;
// each block owns 2 costT rows, processed by the two 128-thread halves in parallel)
__global__ void __launch_bounds__(256)
sinkhorn_fused(const float* __restrict__ cost, const float* __restrict__ costT,
               const float* __restrict__ sT, float* __restrict__ u,
               float* __restrict__ v, float* __restrict__ dsum,
               unsigned* __restrict__ bar, float* __restrict__ out0)
{
    const int tid=threadIdx.x, bid=blockIdx.x;
    const int p = bid*256+tid;
    const int b = p>>12;
    __shared__ float red[256];
    __shared__ float sm[2][128], ssx[2][128];
    const int half = tid>>7, t2 = tid&127;
    const int crow = bid*2 + half;                 // costT row this half owns
    for (int it=0; it<25; ++it){
        {
            const float* vb = v + (b<<5);
            const float4* cp=(const float4*)(cost+((long)p<<5));
            float t[32];
#pragma unroll
            for(int q=0;q<8;q++){
                float4 c4=cp[q];
                t[4*q]=vb[4*q]-c4.x; t[4*q+1]=vb[4*q+1]-c4.y;
                t[4*q+2]=vb[4*q+2]-c4.z; t[4*q+3]=vb[4*q+3]-c4.w;
            }
            float m=t[0];
#pragma unroll
            for(int k=1;k<32;k++) m=fmaxf(m,t[k]);
            float s=0.f;
#pragma unroll
            for(int k=0;k<32;k++) s+=__expf((t[k]-m)*INV_EPS);
            float un=EPSS*LOGP_C-m-EPSS*__logf(s);
            float dl=fabsf(un-u[p]); u[p]=un;
            red[tid]=dl; __syncthreads();
            for(int st=128;st;st>>=1){ if(tid<st) red[tid]+=red[tid+st]; __syncthreads(); }
            if (tid==0) atomicAdd(&dsum[it],red[0]);
        }
        gbar(bar,bar+1,128u);
        {
            const float* row=costT+((long)crow<<12);
            const float* ub=u+((crow>>5)<<12);
            float mm=-CUDART_INF_F, ss=0.f;
            for(int i=t2;i<NPTS;i+=128){
                float x=ub[i]-row[i];
                if (x>mm){ ss=ss*__expf((mm-x)*INV_EPS)+1.f; mm=x; } else ss+=__expf((x-mm)*INV_EPS);
            }
            sm[half][t2]=mm; ssx[half][t2]=ss; __syncthreads();
            for(int st=64;st;st>>=1){
                if(t2<st){
                    float m1=sm[half][t2],s1=ssx[half][t2],m2=sm[half][t2+st],s2=ssx[half][t2+st];
                    float M=fmaxf(m1,m2);
                    ssx[half][t2]=s1*__expf((m1-M)*INV_EPS)+s2*__expf((m2-M)*INV_EPS);
                    sm[half][t2]=M;
                }
                __syncthreads();
            }
            if (t2==0){
                float vn=EPSS*LOGQ_C-sm[half][0]-EPSS*__logf(ssx[half][0]);
                atomicAdd(&dsum[it],fabsf(vn-v[crow]));
                v[crow]=vn;
            }
        }
        gbar(bar,bar+1,128u);
        float dd = *((volatile float*)&dsum[it]);
        if (dd*0.125f < 1e-3f) break;
    }
    {
        const float* vb = v + (b<<5);
        float uu = u[p];
        const float4* cp=(const float4*)(cost+((long)p<<5));
        const float4* sp=(const float4*)(sT+((long)p<<5));
        float acc=0.f;
#pragma unroll
        for(int q=0;q<8;q++){
            float4 c4=cp[q]; float4 s4=sp[q];
            acc+=__expf((uu+vb[4*q]-c4.x)*INV_EPS)*__logf(fmaxf(s4.x,1e-38f));
            acc+=__expf((uu+vb[4*q+1]-c4.y)*INV_EPS)*__logf(fmaxf(s4.y,1e-38f));
            acc+=__expf((uu+vb[4*q+2]-c4.z)*INV_EPS)*__logf(fmaxf(s4.z,1e-38f));
            acc+=__expf((uu+vb[4*q+3]-c4.w)*INV_EPS)*__logf(fmaxf(s4.w,1e-38f));
        }
        red[tid]=acc; __syncthreads();
        for(int st=128;st;st>>=1){ if(tid<st) red[tid]+=red[tid+st]; __syncthreads(); }
        if (tid==0) atomicAdd(out0,red[0]*(-0.125f));
    }
}

template<bool ACT>
__global__ void fc_k(const float* __restrict__ X, const float* __restrict__ W,
                     float* __restrict__ C, int O, int Kin, const float* __restrict__ bias,
                     const float* __restrict__ a, const float* __restrict__ c){
    int gw=(blockIdx.x*256+threadIdx.x)>>5, lane=threadIdx.x&31;
    int b=gw/O, o=gw-b*O;
    const float* x=X+(long)b*Kin;
    const float* wr=W+(long)o*Kin;
    float s=0.f;
    for(int k=lane;k<Kin;k+=32){
        float xv=x[k];
        if (ACT) xv=fmaxf(fmaf(a[k],xv,c[k]),0.f);
        s=fmaf(xv,wr[k],s);
    }
#pragma unroll
    for(int o2=16;o2;o2>>=1) s+=__shfl_xor_sync(~0u,s,o2);
    if(lane==0) C[(long)b*O+o]=s+(bias?bias[o]:0.f);
}

extern "C" void kernel_launch(void* const* d_in, const int* in_sizes, int n_in,
                              void* d_out, int out_size)
{
    const float *F=(const float*)d_in[0];
    const float *cw1=(const float*)d_in[1], *cg1=(const float*)d_in[3], *ct1=(const float*)d_in[4];
    const float *cw2=(const float*)d_in[5], *cg2=(const float*)d_in[7], *ct2=(const float*)d_in[8];
    const float *cw3=(const float*)d_in[9], *cb3=(const float*)d_in[10];
    const float *pw1=(const float*)d_in[11], *pg1=(const float*)d_in[13], *pt1=(const float*)d_in[14];
    const float *pw2=(const float*)d_in[15], *pg2=(const float*)d_in[17], *pt2=(const float*)d_in[18];
    const float *pw3=(const float*)d_in[19], *pb3=(const float*)d_in[20];
    const float *mw1=(const float*)d_in[21], *mg1=(const float*)d_in[23], *mt1=(const float*)d_in[24];
    const float *mw2=(const float*)d_in[25], *mg2=(const float*)d_in[27], *mt2=(const float*)d_in[28];
    const float *mw3=(const float*)d_in[29], *mb3=(const float*)d_in[30];
    float* out=(float*)d_out;

    static float* S=nullptr; static int* FL=nullptr;
    static __nv_bfloat16 *FTh,*FTl,*Fh,*Fl,*Wh,*Wl,*SCh,*SCl,*VTh,*VTl;
    static float *YT,*YT2;
    if (!S){
        cudaGetSymbolAddress((void**)&S,d_scratch);
        cudaGetSymbolAddress((void**)&FL,d_flags);
        cudaGetSymbolAddress((void**)&FTh,d_FTh); cudaGetSymbolAddress((void**)&FTl,d_FTl);
        cudaGetSymbolAddress((void**)&Fh,d_Fh);   cudaGetSymbolAddress((void**)&Fl,d_Fl);
        cudaGetSymbolAddress((void**)&Wh,d_Wh);   cudaGetSymbolAddress((void**)&Wl,d_Wl);
        cudaGetSymbolAddress((void**)&SCh,d_SCh); cudaGetSymbolAddress((void**)&SCl,d_SCl);
        cudaGetSymbolAddress((void**)&VTh,d_VTh); cudaGetSymbolAddress((void**)&VTl,d_VTl);
        cudaGetSymbolAddress((void**)&YT,d_YT);   cudaGetSymbolAddress((void**)&YT2,d_YT2);
        cudaFuncSetAttribute(hmma_gemm<1024,128,2,4,512,false,false>,cudaFuncAttributeMaxDynamicSharedMemorySize,81920);
        cudaFuncSetAttribute(hmma_gemm<512,128,2,4,512,false,true>,cudaFuncAttributeMaxDynamicSharedMemorySize,81920);
        cudaFuncSetAttribute(hmma_gemm<512,32,8,1,32,true,true>,cudaFuncAttributeMaxDynamicSharedMemorySize,51200);
        cudaFuncSetAttribute(hmma_gemm<4096,32,8,1,32,false,false,4,true>,cudaFuncAttributeMaxDynamicSharedMemorySize,51200);
        cudaFuncSetAttribute(hmma_gemm<1024,32,8,1,32,false,false>,cudaFuncAttributeMaxDynamicSharedMemorySize,51200);
    }
    float *LS=S+OFF_LS,*ST=S+OFF_ST,*COST=S+OFF_COST,*COSTT=S+OFF_COSTT;
    float *RN=S+OFF_RN,*POOL=S+OFF_POOL,*P1=S+OFF_P1,*P2=S+OFF_P2;
    float *Z1=S+OFF_Z1,*Z2=S+OFF_Z2,*BNC=S+OFF_BN;
    float *VLAD=S+OFF_VLAD,*PI=S+OFF_PI,*U=S+OFF_U,*V=S+OFF_V,*RMU=S+OFF_RMU;
    float *ACC=S+OFF_ACC,*DS=S+OFF_DSUM;
    float *a1=BNC,*c1=BNC+512,*a2=BNC+1024,*c2=BNC+1536;
    float *ap1=BNC+2048,*cp1=BNC+2560,*ap2=BNC+3072,*cp2=BNC+3584;
    float *am1=BNC+4096,*cm1=BNC+4608,*am2=BNC+5120,*cm2=BNC+5632;

    init_k<<<1,32>>>(FL);
    zero_k<<<(int)((ZTAIL+255)/256),256>>>(S+OFF_VLAD,ZTAIL);
    zero_k<<<129,256>>>(out,32897);
    w_split<<<3137,256>>>(cw1,cw2,cw3,Wh,Wl);
    ft_split<<<dim3(128,32,8),dim3(32,8)>>>(F,FTh,FTl,Fh,Fl,RN);

    // score head on HMMA (bf16x3); BN-relu+split fused into A-load of G2/G3
    hmma_gemm<1024,128,2,4,512,false,false><<<dim3(4,32,8),256,81920>>>(
        FTh,FTl,4194304L, nullptr,nullptr,nullptr, Wh,Wl,0L, YT,2097152L,nullptr);
    bnT_partial<<<128,512>>>(YT,ACC);
    bnT_final<<<1,512>>>(ACC,cg1,ct1,a1,c1);
    hmma_gemm<512,128,2,4,512,false,true><<<dim3(4,32,8),256,81920>>>(
        nullptr,nullptr,2097152L, YT,a1,c1, Wh+524288,Wl+524288,0L, YT2,2097152L,nullptr);
    bnT_partial<<<128,512>>>(YT2,ACC);
    bnT_final<<<1,512>>>(ACC,cg2,ct2,a2,c2);
    hmma_gemm<512,32,8,1,32,true,true><<<dim3(1,32,8),256,51200>>>(
        nullptr,nullptr,2097152L, YT2,a2,c2, Wh+786432,Wl+786432,0L, LS,131072L,cb3);

    softmax_pi<<<4096,256>>>(LS,ST,PI);
    tr_split<<<dim3(128,1,8),dim3(32,8)>>>(ST,SCh,SCl,4096);
    // vlad GEMM with split-K=4 -> 256 CTAs instead of 64
    hmma_gemm<4096,32,8,1,32,false,false,4,true><<<dim3(1,8,32),256,51200>>>(
        Fh,Fl,4194304L, nullptr,nullptr,nullptr, SCh,SCl,131072L, VLAD,32768L,nullptr);
    vlad_fin<<<dim3(4,8),256>>>(VLAD,PI,POOL);
    rmu_k<<<8,1024>>>(VLAD,RMU);
    tr_split<<<dim3(32,1,8),dim3(32,8)>>>(VLAD,VTh,VTl,1024);
    hmma_gemm<1024,32,8,1,32,false,false><<<dim3(1,32,8),256,51200>>>(
        FTh,FTl,4194304L, nullptr,nullptr,nullptr, VTh,VTl,32768L, COST,131072L,nullptr);
    cost_fin<<<dim3(16,8),256>>>(COST,COSTT,RN,RMU);

    sinkhorn_fused<<<128,256>>>(COST,COSTT,ST,U,V,DS,(unsigned*)(FL+2),out);

    gemm_k<128,32,16,8,4,false,8><<<dim3(1,4,64),128>>>(
        pw1,0,DIM, VLAD,(long)DIM*KCL, P1,(long)HID*KCL, HID,KCL,DIM, nullptr,nullptr,nullptr);
    bnproj_stats<<<64,256>>>(P1,pg1,pt1,ap1,cp1,HID);
    gemm_k<128,32,16,8,4,false,8><<<dim3(1,4,64),128>>>(
        pw2,0,HID, P1,(long)HID*KCL, P2,(long)HID*KCL, HID,KCL,HID, nullptr,ap1,cp1);
    bnproj_stats<<<64,256>>>(P2,pg2,pt2,ap2,cp2,HID);
    gemm_k<64,32,16,4,4,false,8><<<dim3(1,2,64),128>>>(
        pw3,0,HID, P2,(long)HID*KCL, out+1,(long)PRJ*KCL, PRJ,KCL,HID, pb3,ap2,cp2);

    fc_k<false><<<512,256>>>(POOL,mw1,Z1,HID,DIM,nullptr,nullptr,nullptr);
    bn2_stats<<<2,256>>>(Z1,mg1,mt1,am1,cm1,HID);
    fc_k<true ><<<512,256>>>(Z1,mw2,Z2,HID,HID,nullptr,am1,cm1);
    bn2_stats<<<2,256>>>(Z2,mg2,mt2,am2,cm2,HID);
    fc_k<true ><<<128,256>>>(Z2,mw3,out+1+32768,PRJ,HID,mb3,am2,cm2);
}